// round 3
// baseline (speedup 1.0000x reference)
#include <cuda_runtime.h>
#include <math.h>

#define NFEAT  6
#define EMBED  256
#define PAIRS  15
#define MROWS  16384          // B*S = 32*512
#define KPAIR  512            // 2*EMBED
#define KFIN   3840           // PAIRS*EMBED

#define BM 128
#define BN 128
#define BK 16
#define NTHREADS 256

// Intermediate H: [MROWS, PAIRS*EMBED] row-major (= flat layout stage 2 consumes).
// 251.7 MB static device global (allocation-guard-safe scratch).
__device__ float g_H[(size_t)MROWS * KFIN];

__constant__ int c_pi[PAIRS] = {0,0,0,0,0,1,1,1,1,2,2,2,3,3,4};
__constant__ int c_pj[PAIRS] = {1,2,3,4,5,2,3,4,5,3,4,5,4,5,5};

__device__ __forceinline__ int pair_mask(const int* __restrict__ NAS, int p) {
    int i = c_pi[p], j = c_pj[p];
    int ni = (i < 2) ? 1 : NAS[i];   // encoder_input=True forces first two on
    int nj = (j < 2) ? 1 : NAS[j];
    return ni * nj;
}

// ---------------------------------------------------------------------------
// Stage 1: for pair p, H[:, p*256 : (p+1)*256] = tanh([Fi|Fj] @ W_pair[p] + b_pair[p])
// Masked pairs: early-exit (stage 2 never reads those columns).
// Classic 128x128x16 sgemm, 256 threads, 8x8 per-thread tile split 4+4 (+64).
// ---------------------------------------------------------------------------
__global__ __launch_bounds__(NTHREADS)
void stage1_kernel(const float* __restrict__ features,
                   const float* __restrict__ W_pair,
                   const float* __restrict__ b_pair,
                   const int*   __restrict__ NAS)
{
    const int p = blockIdx.z;
    if (pair_mask(NAS, p) == 0) return;

    __shared__ float As[BK][BM];
    __shared__ float Bs[BK][BN];

    const int rowBase = blockIdx.y * BM;
    const int colBase = blockIdx.x * BN;
    const int tid = threadIdx.x;

    const float* Fi = features + (size_t)c_pi[p] * MROWS * EMBED;
    const float* Fj = features + (size_t)c_pj[p] * MROWS * EMBED;
    const float* Wp = W_pair   + (size_t)p * KPAIR * EMBED;

    // loader lanes
    const int aRow = tid >> 2;            // 0..63
    const int aCol = (tid & 3) << 2;      // 0,4,8,12
    const int bRow = tid >> 5;            // 0..7
    const int bCol = (tid & 31) << 2;     // 0..124

    // compute lanes: rows rBase..+3 and rBase+64..+67; cols cBase..+3 and cBase+64..+67
    const int rBase = ((tid >> 4) & 15) << 2;
    const int cBase = (tid & 15) << 2;

    float acc[8][8];
    #pragma unroll
    for (int i = 0; i < 8; i++)
        #pragma unroll
        for (int j = 0; j < 8; j++) acc[i][j] = 0.0f;

    for (int k0 = 0; k0 < KPAIR; k0 += BK) {
        // concat gather: first 256 K-columns come from Fi, rest from Fj
        const float* Xb = (k0 < EMBED) ? (Fi + k0) : (Fj + (k0 - EMBED));
        #pragma unroll
        for (int r = 0; r < 2; r++) {
            int row = aRow + r * 64;
            float4 v = *reinterpret_cast<const float4*>(
                Xb + (size_t)(rowBase + row) * EMBED + aCol);
            As[aCol + 0][row] = v.x;
            As[aCol + 1][row] = v.y;
            As[aCol + 2][row] = v.z;
            As[aCol + 3][row] = v.w;
        }
        #pragma unroll
        for (int r = 0; r < 2; r++) {
            int krow = bRow + r * 8;
            *reinterpret_cast<float4*>(&Bs[krow][bCol]) =
                *reinterpret_cast<const float4*>(
                    Wp + (size_t)(k0 + krow) * EMBED + colBase + bCol);
        }
        __syncthreads();

        #pragma unroll
        for (int k = 0; k < BK; k++) {
            float4 a0 = *reinterpret_cast<const float4*>(&As[k][rBase]);
            float4 a1 = *reinterpret_cast<const float4*>(&As[k][rBase + 64]);
            float4 b0 = *reinterpret_cast<const float4*>(&Bs[k][cBase]);
            float4 b1 = *reinterpret_cast<const float4*>(&Bs[k][cBase + 64]);
            float ra[8] = {a0.x, a0.y, a0.z, a0.w, a1.x, a1.y, a1.z, a1.w};
            float rb[8] = {b0.x, b0.y, b0.z, b0.w, b1.x, b1.y, b1.z, b1.w};
            #pragma unroll
            for (int i = 0; i < 8; i++)
                #pragma unroll
                for (int j = 0; j < 8; j++)
                    acc[i][j] += ra[i] * rb[j];
        }
        __syncthreads();
    }

    // epilogue: bias + tanh, write H
    const float* bp = b_pair + p * EMBED + colBase;
    float bias[8];
    #pragma unroll
    for (int j = 0; j < 8; j++)
        bias[j] = bp[(j < 4) ? (cBase + j) : (cBase + 60 + j)];

    #pragma unroll
    for (int i = 0; i < 8; i++) {
        int row = rowBase + ((i < 4) ? (rBase + i) : (rBase + 60 + i));
        float* dst = g_H + (size_t)row * KFIN + p * EMBED + colBase;
        float4 v0, v1;
        v0.x = tanhf(acc[i][0] + bias[0]);
        v0.y = tanhf(acc[i][1] + bias[1]);
        v0.z = tanhf(acc[i][2] + bias[2]);
        v0.w = tanhf(acc[i][3] + bias[3]);
        v1.x = tanhf(acc[i][4] + bias[4]);
        v1.y = tanhf(acc[i][5] + bias[5]);
        v1.z = tanhf(acc[i][6] + bias[6]);
        v1.w = tanhf(acc[i][7] + bias[7]);
        *reinterpret_cast<float4*>(dst + cBase)      = v0;
        *reinterpret_cast<float4*>(dst + cBase + 64) = v1;
    }
}

// ---------------------------------------------------------------------------
// Stage 2: out = H @ W_final + b_final, skipping K-segments of masked pairs.
// ---------------------------------------------------------------------------
__global__ __launch_bounds__(NTHREADS)
void stage2_kernel(const float* __restrict__ W_final,
                   const float* __restrict__ b_final,
                   const int*   __restrict__ NAS,
                   float*       __restrict__ out)
{
    __shared__ float As[BK][BM];
    __shared__ float Bs[BK][BN];

    const int rowBase = blockIdx.y * BM;
    const int colBase = blockIdx.x * BN;
    const int tid = threadIdx.x;

    const int aRow = tid >> 2;
    const int aCol = (tid & 3) << 2;
    const int bRow = tid >> 5;
    const int bCol = (tid & 31) << 2;
    const int rBase = ((tid >> 4) & 15) << 2;
    const int cBase = (tid & 15) << 2;

    // active-pair bitmask (uniform across block)
    int pmask = 0;
    #pragma unroll
    for (int p = 0; p < PAIRS; p++)
        pmask |= pair_mask(NAS, p) << p;

    float acc[8][8];
    #pragma unroll
    for (int i = 0; i < 8; i++)
        #pragma unroll
        for (int j = 0; j < 8; j++) acc[i][j] = 0.0f;

    for (int p = 0; p < PAIRS; p++) {
        if (!((pmask >> p) & 1)) continue;
        for (int kk = 0; kk < EMBED; kk += BK) {
            const int k0 = p * EMBED + kk;
            #pragma unroll
            for (int r = 0; r < 2; r++) {
                int row = aRow + r * 64;
                float4 v = *reinterpret_cast<const float4*>(
                    g_H + (size_t)(rowBase + row) * KFIN + k0 + aCol);
                As[aCol + 0][row] = v.x;
                As[aCol + 1][row] = v.y;
                As[aCol + 2][row] = v.z;
                As[aCol + 3][row] = v.w;
            }
            #pragma unroll
            for (int r = 0; r < 2; r++) {
                int krow = bRow + r * 8;
                *reinterpret_cast<float4*>(&Bs[krow][bCol]) =
                    *reinterpret_cast<const float4*>(
                        W_final + (size_t)(k0 + krow) * EMBED + colBase + bCol);
            }
            __syncthreads();

            #pragma unroll
            for (int k = 0; k < BK; k++) {
                float4 a0 = *reinterpret_cast<const float4*>(&As[k][rBase]);
                float4 a1 = *reinterpret_cast<const float4*>(&As[k][rBase + 64]);
                float4 b0 = *reinterpret_cast<const float4*>(&Bs[k][cBase]);
                float4 b1 = *reinterpret_cast<const float4*>(&Bs[k][cBase + 64]);
                float ra[8] = {a0.x, a0.y, a0.z, a0.w, a1.x, a1.y, a1.z, a1.w};
                float rb[8] = {b0.x, b0.y, b0.z, b0.w, b1.x, b1.y, b1.z, b1.w};
                #pragma unroll
                for (int i = 0; i < 8; i++)
                    #pragma unroll
                    for (int j = 0; j < 8; j++)
                        acc[i][j] += ra[i] * rb[j];
            }
            __syncthreads();
        }
    }

    // epilogue: + b_final
    const float* bf = b_final + colBase;
    float bias[8];
    #pragma unroll
    for (int j = 0; j < 8; j++)
        bias[j] = bf[(j < 4) ? (cBase + j) : (cBase + 60 + j)];

    #pragma unroll
    for (int i = 0; i < 8; i++) {
        int row = rowBase + ((i < 4) ? (rBase + i) : (rBase + 60 + i));
        float* dst = out + (size_t)row * EMBED + colBase;
        float4 v0, v1;
        v0.x = acc[i][0] + bias[0];
        v0.y = acc[i][1] + bias[1];
        v0.z = acc[i][2] + bias[2];
        v0.w = acc[i][3] + bias[3];
        v1.x = acc[i][4] + bias[4];
        v1.y = acc[i][5] + bias[5];
        v1.z = acc[i][6] + bias[6];
        v1.w = acc[i][7] + bias[7];
        *reinterpret_cast<float4*>(dst + cBase)      = v0;
        *reinterpret_cast<float4*>(dst + cBase + 64) = v1;
    }
}

extern "C" void kernel_launch(void* const* d_in, const int* in_sizes, int n_in,
                              void* d_out, int out_size)
{
    const float* features = (const float*)d_in[0];
    const float* W_pair   = (const float*)d_in[1];
    const float* b_pair   = (const float*)d_in[2];
    const float* W_final  = (const float*)d_in[3];
    const float* b_final  = (const float*)d_in[4];
    const int*   NAS      = (const int*)d_in[5];
    float* out = (float*)d_out;

    dim3 g1(EMBED / BN, MROWS / BM, PAIRS);   // (2, 128, 15)
    dim3 g2(EMBED / BN, MROWS / BM);          // (2, 128)

    stage1_kernel<<<g1, NTHREADS>>>(features, W_pair, b_pair, NAS);
    stage2_kernel<<<g2, NTHREADS>>>(W_final, b_final, NAS, out);
}

// round 6
// speedup vs baseline: 2.1264x; 2.1264x over previous
#include <cuda_runtime.h>
#include <cuda_fp16.h>
#include <cstdint>
#include <math.h>

#define EMBED 256
#define PAIRS 15
#define MROWS 16384
#define KPAIR 512
#define KFIN  3840

#define BM 128
#define BN 128
#define KC 32
#define NTHREADS 256
#define PITCH 80                         // smem row: 32 fp16 = 64B data + 16B pad
#define TILE (128 * PITCH)               // 10240 B
#define BUFBYTES (4 * TILE)              // Ahi, Alo, Bhi, Blo
#define SMEM_BYTES (2 * BUFBYTES)        // 81920 B (double buffered)

// ---- pre-split fp16 scratch (static device globals; allocation-guard-safe) ----
static __device__ __half g_Fhi[(size_t)6 * MROWS * EMBED];
static __device__ __half g_Flo[(size_t)6 * MROWS * EMBED];
static __device__ __half g_Hhi[(size_t)MROWS * KFIN];
static __device__ __half g_Hlo[(size_t)MROWS * KFIN];
static __device__ __half g_Wpt_hi[(size_t)PAIRS * EMBED * KPAIR];  // [p][n][k]
static __device__ __half g_Wpt_lo[(size_t)PAIRS * EMBED * KPAIR];
static __device__ __half g_Wft_hi[(size_t)EMBED * KFIN];           // [n][k]
static __device__ __half g_Wft_lo[(size_t)EMBED * KFIN];

__constant__ int c_pi[PAIRS] = {0,0,0,0,0,1,1,1,1,2,2,2,3,3,4};
__constant__ int c_pj[PAIRS] = {1,2,3,4,5,2,3,4,5,3,4,5,4,5,5};

__device__ __forceinline__ bool pair_on(const int* __restrict__ NAS, int p) {
    int i = c_pi[p], j = c_pj[p];
    int ni = (i < 2) ? 1 : __ldg(&NAS[i]);
    int nj = (j < 2) ? 1 : __ldg(&NAS[j]);
    return (ni != 0) && (nj != 0);
}
__device__ __forceinline__ void split_h(float x, __half& h, __half& l) {
    h = __float2half_rn(x);
    l = __float2half_rn(x - __half2float(h));
}
__device__ __forceinline__ uint32_t smem_u32(const void* p) {
    uint32_t a;
    asm("{ .reg .u64 t; cvta.to.shared.u64 t, %1; cvt.u32.u64 %0, t; }" : "=r"(a) : "l"(p));
    return a;
}

// ---- base-target PTX primitives (all valid on sm_103 / sm_80+) ----
__device__ __forceinline__ void cp16(uint32_t dst, const void* src) {
    asm volatile("cp.async.ca.shared.global [%0], [%1], 16;" :: "r"(dst), "l"(src));
}
#define CP_COMMIT()      asm volatile("cp.async.commit_group;" ::: "memory")
#define CP_WAIT(n)       asm volatile("cp.async.wait_group %0;" :: "n"(n) : "memory")
#define LDM_X4(r, addr) \
    asm volatile("ldmatrix.sync.aligned.m8n8.x4.shared.b16 {%0,%1,%2,%3}, [%4];" \
        : "=r"((r)[0]), "=r"((r)[1]), "=r"((r)[2]), "=r"((r)[3]) : "r"(addr))
#define LDS32(v, addr) \
    asm volatile("ld.shared.b32 %0, [%1];" : "=r"(v) : "r"(addr))
#define MMA(d, a, b0, b1) \
    asm volatile("mma.sync.aligned.m16n8k16.row.col.f32.f16.f16.f32 " \
        "{%0,%1,%2,%3}, {%4,%5,%6,%7}, {%8,%9}, {%0,%1,%2,%3};" \
        : "+f"((d)[0]), "+f"((d)[1]), "+f"((d)[2]), "+f"((d)[3]) \
        : "r"((a)[0]), "r"((a)[1]), "r"((a)[2]), "r"((a)[3]), "r"(b0), "r"(b1))

// ---------------------------------------------------------------------------
// Prep kernels: fp32 -> split fp16 (hi + lo), weights also transposed to [n][k].
// ---------------------------------------------------------------------------
__global__ void prep_feat(const float* __restrict__ features, const int* __restrict__ NAS) {
    int f = blockIdx.y;
    if (f >= 2 && __ldg(&NAS[f]) == 0) return;   // unused feature (partners 0,1 always on)
    size_t base = (size_t)f * MROWS * EMBED;
    size_t i = ((size_t)blockIdx.x * blockDim.x + threadIdx.x) * 4;
    float4 v = *reinterpret_cast<const float4*>(features + base + i);
    __half h0,l0,h1,l1,h2,l2,h3,l3;
    split_h(v.x, h0, l0); split_h(v.y, h1, l1);
    split_h(v.z, h2, l2); split_h(v.w, h3, l3);
    *reinterpret_cast<__half2*>(g_Fhi + base + i)     = __halves2half2(h0, h1);
    *reinterpret_cast<__half2*>(g_Fhi + base + i + 2) = __halves2half2(h2, h3);
    *reinterpret_cast<__half2*>(g_Flo + base + i)     = __halves2half2(l0, l1);
    *reinterpret_cast<__half2*>(g_Flo + base + i + 2) = __halves2half2(l2, l3);
}

__global__ void prep_wpair(const float* __restrict__ W_pair, const int* __restrict__ NAS) {
    int p = blockIdx.z;
    if (!pair_on(NAS, p)) return;
    __shared__ float tsh[32][33];
    int k0 = blockIdx.x * 32, n0 = blockIdx.y * 32;
    int tx = threadIdx.x, ty = threadIdx.y;
    const float* W = W_pair + (size_t)p * KPAIR * EMBED;
    #pragma unroll
    for (int i = 0; i < 4; i++)
        tsh[ty + i*8][tx] = W[(size_t)(k0 + ty + i*8) * EMBED + n0 + tx];
    __syncthreads();
    #pragma unroll
    for (int i = 0; i < 4; i++) {
        float v = tsh[tx][ty + i*8];
        __half h, l; split_h(v, h, l);
        size_t o = ((size_t)p * EMBED + n0 + ty + i*8) * KPAIR + k0 + tx;
        g_Wpt_hi[o] = h; g_Wpt_lo[o] = l;
    }
}

__global__ void prep_wfinal(const float* __restrict__ W_final, const int* __restrict__ NAS) {
    int k0 = blockIdx.x * 32;
    if (!pair_on(NAS, k0 >> 8)) return;          // skip masked 256-wide K segment
    __shared__ float tsh[32][33];
    int n0 = blockIdx.y * 32;
    int tx = threadIdx.x, ty = threadIdx.y;
    #pragma unroll
    for (int i = 0; i < 4; i++)
        tsh[ty + i*8][tx] = W_final[(size_t)(k0 + ty + i*8) * EMBED + n0 + tx];
    __syncthreads();
    #pragma unroll
    for (int i = 0; i < 4; i++) {
        float v = tsh[tx][ty + i*8];
        __half h, l; split_h(v, h, l);
        size_t o = (size_t)(n0 + ty + i*8) * KFIN + k0 + tx;
        g_Wft_hi[o] = h; g_Wft_lo[o] = l;
    }
}

// ---------------------------------------------------------------------------
// GEMM building blocks (shared by both stages).
// smem chunk layout per buffer: [Ahi 128xKC][Alo][Bhi][Blo], row pitch 80B.
// ---------------------------------------------------------------------------
__device__ __forceinline__ void load_chunk_tiles(
    uint32_t sdst_base, int tid,
    const __half* aH, const __half* aL, size_t strideA,
    const __half* bH, const __half* bL, size_t strideB)
{
    const int row = tid >> 1, half = tid & 1;
    const uint32_t d = sdst_base + row * PITCH + half * 32;
    const __half* a0 = aH + (size_t)row * strideA + half * 16;
    const __half* a1 = aL + (size_t)row * strideA + half * 16;
    const __half* b0 = bH + (size_t)row * strideB + half * 16;
    const __half* b1 = bL + (size_t)row * strideB + half * 16;
    cp16(d,               a0); cp16(d + 16,            a0 + 8);
    cp16(d + TILE,        a1); cp16(d + TILE + 16,     a1 + 8);
    cp16(d + 2*TILE,      b0); cp16(d + 2*TILE + 16,   b0 + 8);
    cp16(d + 3*TILE,      b1); cp16(d + 3*TILE + 16,   b1 + 8);
}

__device__ __forceinline__ void compute_chunk(
    uint32_t sbase, int warpM, int warpN, int lid, float acc[2][8][4])
{
    const int arow = lid & 15, ka = (lid >> 4) & 1;
    const int g = lid >> 2, t = lid & 3;
    #pragma unroll
    for (int ks = 0; ks < 2; ks++) {
        uint32_t ahi[2][4], alo[2][4];
        #pragma unroll
        for (int mt = 0; mt < 2; mt++) {
            uint32_t ad = sbase + (warpM*32 + mt*16 + arow) * PITCH + ks*32 + ka*16;
            LDM_X4(ahi[mt], ad);
            LDM_X4(alo[mt], ad + TILE);
        }
        #pragma unroll
        for (int nt = 0; nt < 8; nt++) {
            uint32_t bd = sbase + 2*TILE + (warpN*64 + nt*8 + g) * PITCH + ks*32 + t*4;
            uint32_t bh0, bh1, bl0, bl1;
            LDS32(bh0, bd);        LDS32(bh1, bd + 16);
            LDS32(bl0, bd + TILE); LDS32(bl1, bd + TILE + 16);
            MMA(acc[0][nt], ahi[0], bh0, bh1);   // hi*hi
            MMA(acc[1][nt], ahi[1], bh0, bh1);
            MMA(acc[0][nt], ahi[0], bl0, bl1);   // hi*lo
            MMA(acc[1][nt], ahi[1], bl0, bl1);
            MMA(acc[0][nt], alo[0], bh0, bh1);   // lo*hi
            MMA(acc[1][nt], alo[1], bh0, bh1);
        }
    }
}

// ---------------------------------------------------------------------------
// Stage 1: H[:, p*256:(p+1)*256] = tanh([Fi|Fj] @ W_pair[p] + b_pair[p])
// ---------------------------------------------------------------------------
__global__ __launch_bounds__(NTHREADS, 1)
void stage1_mma(const float* __restrict__ b_pair, const int* __restrict__ NAS)
{
    const int p = blockIdx.z;
    if (!pair_on(NAS, p)) return;
    const int colTile = blockIdx.x;
    const int rowBase = blockIdx.y * BM;

    extern __shared__ char smem[];
    const uint32_t sb = smem_u32(smem);
    const int tid = threadIdx.x, wid = tid >> 5, lid = tid & 31;
    const int warpM = wid & 3, warpN = wid >> 2;

    const __half* FiH = g_Fhi + (size_t)c_pi[p] * MROWS * EMBED + (size_t)rowBase * EMBED;
    const __half* FiL = g_Flo + (size_t)c_pi[p] * MROWS * EMBED + (size_t)rowBase * EMBED;
    const __half* FjH = g_Fhi + (size_t)c_pj[p] * MROWS * EMBED + (size_t)rowBase * EMBED;
    const __half* FjL = g_Flo + (size_t)c_pj[p] * MROWS * EMBED + (size_t)rowBase * EMBED;
    const __half* WH = g_Wpt_hi + ((size_t)p * EMBED + colTile * 128) * KPAIR;
    const __half* WL = g_Wpt_lo + ((size_t)p * EMBED + colTile * 128) * KPAIR;

    float acc[2][8][4];
    #pragma unroll
    for (int i = 0; i < 2; i++)
        #pragma unroll
        for (int j = 0; j < 8; j++)
            #pragma unroll
            for (int e = 0; e < 4; e++) acc[i][j][e] = 0.0f;

    const int NCH = KPAIR / KC;   // 16
    {   // prologue
        load_chunk_tiles(sb, tid, FiH, FiL, EMBED, WH, WL, KPAIR);
        CP_COMMIT();
    }
    for (int c = 0; c < NCH; c++) {
        const int cur = c & 1;
        if (c + 1 < NCH) {
            const int k0 = (c + 1) * KC;
            const __half* aH = (k0 < EMBED) ? (FiH + k0) : (FjH + (k0 - EMBED));
            const __half* aL = (k0 < EMBED) ? (FiL + k0) : (FjL + (k0 - EMBED));
            load_chunk_tiles(sb + (1 - cur) * BUFBYTES, tid, aH, aL, EMBED,
                             WH + k0, WL + k0, KPAIR);
            CP_COMMIT();
            CP_WAIT(1);
        } else {
            CP_WAIT(0);
        }
        __syncthreads();
        compute_chunk(sb + cur * BUFBYTES, warpM, warpN, lid, acc);
        __syncthreads();
    }

    // epilogue: bias + tanh, split -> fp16 hi/lo, store H
    const int g = lid >> 2, t = lid & 3;
    #pragma unroll
    for (int mt = 0; mt < 2; mt++) {
        const int r0 = rowBase + warpM * 32 + mt * 16 + g;
        #pragma unroll
        for (int nt = 0; nt < 8; nt++) {
            const int colP = colTile * 128 + warpN * 64 + nt * 8 + 2 * t;
            const float b0 = __ldg(&b_pair[p * EMBED + colP]);
            const float b1 = __ldg(&b_pair[p * EMBED + colP + 1]);
            float v00 = tanhf(acc[mt][nt][0] + b0);
            float v01 = tanhf(acc[mt][nt][1] + b1);
            float v10 = tanhf(acc[mt][nt][2] + b0);
            float v11 = tanhf(acc[mt][nt][3] + b1);
            __half h0,l0,h1,l1;
            size_t o0 = (size_t)r0 * KFIN + (size_t)p * EMBED + colP;
            size_t o1 = o0 + (size_t)8 * KFIN;
            split_h(v00, h0, l0); split_h(v01, h1, l1);
            *reinterpret_cast<__half2*>(g_Hhi + o0) = __halves2half2(h0, h1);
            *reinterpret_cast<__half2*>(g_Hlo + o0) = __halves2half2(l0, l1);
            split_h(v10, h0, l0); split_h(v11, h1, l1);
            *reinterpret_cast<__half2*>(g_Hhi + o1) = __halves2half2(h0, h1);
            *reinterpret_cast<__half2*>(g_Hlo + o1) = __halves2half2(l0, l1);
        }
    }
}

// ---------------------------------------------------------------------------
// Stage 2: out = H @ W_final + b_final over active 256-wide K segments.
// ---------------------------------------------------------------------------
__global__ __launch_bounds__(NTHREADS, 1)
void stage2_mma(const float* __restrict__ b_final, const int* __restrict__ NAS,
                float* __restrict__ out)
{
    const int colTile = blockIdx.x;
    const int rowBase = blockIdx.y * BM;

    extern __shared__ char smem[];
    const uint32_t sb = smem_u32(smem);
    const int tid = threadIdx.x, wid = tid >> 5, lid = tid & 31;
    const int warpM = wid & 3, warpN = wid >> 2;

    int plist[PAIRS], nact = 0;
    #pragma unroll
    for (int p = 0; p < PAIRS; p++)
        if (pair_on(NAS, p)) plist[nact++] = p;
    const int NCH = nact * (EMBED / KC);   // nact * 8

    const __half* AH = g_Hhi + (size_t)rowBase * KFIN;
    const __half* AL = g_Hlo + (size_t)rowBase * KFIN;
    const __half* BH = g_Wft_hi + (size_t)colTile * 128 * KFIN;
    const __half* BL = g_Wft_lo + (size_t)colTile * 128 * KFIN;

    float acc[2][8][4];
    #pragma unroll
    for (int i = 0; i < 2; i++)
        #pragma unroll
        for (int j = 0; j < 8; j++)
            #pragma unroll
            for (int e = 0; e < 4; e++) acc[i][j][e] = 0.0f;

    {   // prologue (chunk 0)
        const int kcol = plist[0] * EMBED;
        load_chunk_tiles(sb, tid, AH + kcol, AL + kcol, KFIN, BH + kcol, BL + kcol, KFIN);
        CP_COMMIT();
    }
    for (int c = 0; c < NCH; c++) {
        const int cur = c & 1;
        if (c + 1 < NCH) {
            const int i = c + 1;
            const int kcol = plist[i >> 3] * EMBED + (i & 7) * KC;
            load_chunk_tiles(sb + (1 - cur) * BUFBYTES, tid,
                             AH + kcol, AL + kcol, KFIN, BH + kcol, BL + kcol, KFIN);
            CP_COMMIT();
            CP_WAIT(1);
        } else {
            CP_WAIT(0);
        }
        __syncthreads();
        compute_chunk(sb + cur * BUFBYTES, warpM, warpN, lid, acc);
        __syncthreads();
    }

    // epilogue: + b_final, fp32 out
    const int g = lid >> 2, t = lid & 3;
    #pragma unroll
    for (int mt = 0; mt < 2; mt++) {
        const int r0 = rowBase + warpM * 32 + mt * 16 + g;
        #pragma unroll
        for (int nt = 0; nt < 8; nt++) {
            const int colG = colTile * 128 + warpN * 64 + nt * 8 + 2 * t;
            const float b0 = __ldg(&b_final[colG]);
            const float b1 = __ldg(&b_final[colG + 1]);
            float2 w0 = make_float2(acc[mt][nt][0] + b0, acc[mt][nt][1] + b1);
            float2 w1 = make_float2(acc[mt][nt][2] + b0, acc[mt][nt][3] + b1);
            *reinterpret_cast<float2*>(out + (size_t)r0 * EMBED + colG)       = w0;
            *reinterpret_cast<float2*>(out + (size_t)(r0 + 8) * EMBED + colG) = w1;
        }
    }
}

extern "C" void kernel_launch(void* const* d_in, const int* in_sizes, int n_in,
                              void* d_out, int out_size)
{
    const float* features = (const float*)d_in[0];
    const float* W_pair   = (const float*)d_in[1];
    const float* b_pair   = (const float*)d_in[2];
    const float* W_final  = (const float*)d_in[3];
    const float* b_final  = (const float*)d_in[4];
    const int*   NAS      = (const int*)d_in[5];
    float* out = (float*)d_out;

    cudaFuncSetAttribute(stage1_mma, cudaFuncAttributeMaxDynamicSharedMemorySize, SMEM_BYTES);
    cudaFuncSetAttribute(stage2_mma, cudaFuncAttributeMaxDynamicSharedMemorySize, SMEM_BYTES);

    // MROWS*EMBED/4 float4 per feature / 256 threads = 4096 blocks
    prep_feat  <<<dim3(4096, 6),   256>>>(features, NAS);
    prep_wpair <<<dim3(KPAIR/32, EMBED/32, PAIRS), dim3(32, 8)>>>(W_pair, NAS);
    prep_wfinal<<<dim3(KFIN/32,  EMBED/32),        dim3(32, 8)>>>(W_final, NAS);

    stage1_mma<<<dim3(2, MROWS/BM, PAIRS), NTHREADS, SMEM_BYTES>>>(b_pair, NAS);
    stage2_mma<<<dim3(2, MROWS/BM),        NTHREADS, SMEM_BYTES>>>(b_final, NAS, out);
}

// round 7
// speedup vs baseline: 2.2211x; 1.0446x over previous
#include <cuda_runtime.h>
#include <cuda_fp16.h>
#include <cstdint>
#include <math.h>

#define EMBED 256
#define PAIRS 15
#define MROWS 16384
#define KPAIR 512
#define KFIN  3840

#define BM 128
#define BN 256
#define KC 32
#define NTHREADS 256
#define PITCH 80                         // smem row: 32 fp16 = 64B data + 16B pad
#define ATILE (128 * PITCH)              // 10240 B
#define BTILE (256 * PITCH)              // 20480 B
#define BUFBYTES (2 * ATILE + 2 * BTILE) // 61440 B  [Ahi][Alo][Bhi][Blo]
#define SMEM_BYTES (2 * BUFBYTES)        // 122880 B (double buffered)

// ---- pre-split fp16 scratch (static device globals; allocation-guard-safe) ----
static __device__ __half g_Fhi[(size_t)6 * MROWS * EMBED];
static __device__ __half g_Flo[(size_t)6 * MROWS * EMBED];
static __device__ __half g_Hhi[(size_t)MROWS * KFIN];
static __device__ __half g_Hlo[(size_t)MROWS * KFIN];
static __device__ __half g_Wpt_hi[(size_t)PAIRS * EMBED * KPAIR];  // [p][n][k]
static __device__ __half g_Wpt_lo[(size_t)PAIRS * EMBED * KPAIR];
static __device__ __half g_Wft_hi[(size_t)EMBED * KFIN];           // [n][k]
static __device__ __half g_Wft_lo[(size_t)EMBED * KFIN];

__constant__ int c_pi[PAIRS] = {0,0,0,0,0,1,1,1,1,2,2,2,3,3,4};
__constant__ int c_pj[PAIRS] = {1,2,3,4,5,2,3,4,5,3,4,5,4,5,5};

__device__ __forceinline__ bool pair_on(const int* __restrict__ NAS, int p) {
    int i = c_pi[p], j = c_pj[p];
    int ni = (i < 2) ? 1 : __ldg(&NAS[i]);
    int nj = (j < 2) ? 1 : __ldg(&NAS[j]);
    return (ni != 0) && (nj != 0);
}
__device__ __forceinline__ void split_h(float x, __half& h, __half& l) {
    h = __float2half_rn(x);
    l = __float2half_rn(x - __half2float(h));
}
__device__ __forceinline__ uint32_t smem_u32(const void* p) {
    uint32_t a;
    asm("{ .reg .u64 t; cvta.to.shared.u64 t, %1; cvt.u32.u64 %0, t; }" : "=r"(a) : "l"(p));
    return a;
}

// ---- base-target PTX primitives (sm_80 baseline; valid on plain sm_103) ----
__device__ __forceinline__ void cp16(uint32_t dst, const void* src) {
    asm volatile("cp.async.cg.shared.global [%0], [%1], 16;" :: "r"(dst), "l"(src));
}
#define CP_COMMIT()      asm volatile("cp.async.commit_group;" ::: "memory")
#define CP_WAIT(n)       asm volatile("cp.async.wait_group %0;" :: "n"(n) : "memory")
#define LDM_X4(r, addr) \
    asm volatile("ldmatrix.sync.aligned.m8n8.x4.shared.b16 {%0,%1,%2,%3}, [%4];" \
        : "=r"((r)[0]), "=r"((r)[1]), "=r"((r)[2]), "=r"((r)[3]) : "r"(addr))
#define LDS32(v, addr) \
    asm volatile("ld.shared.b32 %0, [%1];" : "=r"(v) : "r"(addr))
#define MMA(d, a, b0, b1) \
    asm volatile("mma.sync.aligned.m16n8k16.row.col.f32.f16.f16.f32 " \
        "{%0,%1,%2,%3}, {%4,%5,%6,%7}, {%8,%9}, {%0,%1,%2,%3};" \
        : "+f"((d)[0]), "+f"((d)[1]), "+f"((d)[2]), "+f"((d)[3]) \
        : "r"((a)[0]), "r"((a)[1]), "r"((a)[2]), "r"((a)[3]), "r"(b0), "r"(b1))

// ---------------------------------------------------------------------------
// Prep kernels: fp32 -> split fp16 (hi + lo), weights also transposed to [n][k].
// ---------------------------------------------------------------------------
__global__ void prep_feat(const float* __restrict__ features, const int* __restrict__ NAS) {
    int f = blockIdx.y;
    if (f >= 2 && __ldg(&NAS[f]) == 0) return;
    size_t base = (size_t)f * MROWS * EMBED;
    size_t i = ((size_t)blockIdx.x * blockDim.x + threadIdx.x) * 4;
    float4 v = *reinterpret_cast<const float4*>(features + base + i);
    __half h0,l0,h1,l1,h2,l2,h3,l3;
    split_h(v.x, h0, l0); split_h(v.y, h1, l1);
    split_h(v.z, h2, l2); split_h(v.w, h3, l3);
    *reinterpret_cast<__half2*>(g_Fhi + base + i)     = __halves2half2(h0, h1);
    *reinterpret_cast<__half2*>(g_Fhi + base + i + 2) = __halves2half2(h2, h3);
    *reinterpret_cast<__half2*>(g_Flo + base + i)     = __halves2half2(l0, l1);
    *reinterpret_cast<__half2*>(g_Flo + base + i + 2) = __halves2half2(l2, l3);
}

__global__ void prep_wpair(const float* __restrict__ W_pair, const int* __restrict__ NAS) {
    int p = blockIdx.z;
    if (!pair_on(NAS, p)) return;
    __shared__ float tsh[32][33];
    int k0 = blockIdx.x * 32, n0 = blockIdx.y * 32;
    int tx = threadIdx.x, ty = threadIdx.y;
    const float* W = W_pair + (size_t)p * KPAIR * EMBED;
    #pragma unroll
    for (int i = 0; i < 4; i++)
        tsh[ty + i*8][tx] = W[(size_t)(k0 + ty + i*8) * EMBED + n0 + tx];
    __syncthreads();
    #pragma unroll
    for (int i = 0; i < 4; i++) {
        float v = tsh[tx][ty + i*8];
        __half h, l; split_h(v, h, l);
        size_t o = ((size_t)p * EMBED + n0 + ty + i*8) * KPAIR + k0 + tx;
        g_Wpt_hi[o] = h; g_Wpt_lo[o] = l;
    }
}

__global__ void prep_wfinal(const float* __restrict__ W_final, const int* __restrict__ NAS) {
    int k0 = blockIdx.x * 32;
    if (!pair_on(NAS, k0 >> 8)) return;
    __shared__ float tsh[32][33];
    int n0 = blockIdx.y * 32;
    int tx = threadIdx.x, ty = threadIdx.y;
    #pragma unroll
    for (int i = 0; i < 4; i++)
        tsh[ty + i*8][tx] = W_final[(size_t)(k0 + ty + i*8) * EMBED + n0 + tx];
    __syncthreads();
    #pragma unroll
    for (int i = 0; i < 4; i++) {
        float v = tsh[tx][ty + i*8];
        __half h, l; split_h(v, h, l);
        size_t o = (size_t)(n0 + ty + i*8) * KFIN + k0 + tx;
        g_Wft_hi[o] = h; g_Wft_lo[o] = l;
    }
}

// ---------------------------------------------------------------------------
// GEMM building blocks. Buffer: [Ahi 128xKC][Alo][Bhi 256xKC][Blo], pitch 80B.
// ---------------------------------------------------------------------------
__device__ __forceinline__ void load_chunk_tiles(
    uint32_t buf, int tid,
    const __half* aH, const __half* aL, size_t strideA,
    const __half* bH, const __half* bL, size_t strideB)
{
    // A: 2 threads per row (128 rows)
    {
        const int row = tid >> 1, half = tid & 1;
        const uint32_t d = buf + row * PITCH + half * 32;
        const __half* s0 = aH + (size_t)row * strideA + half * 16;
        const __half* s1 = aL + (size_t)row * strideA + half * 16;
        cp16(d,          s0); cp16(d + 16,          s0 + 8);
        cp16(d + ATILE,  s1); cp16(d + ATILE + 16,  s1 + 8);
    }
    // B: 1 thread per row (256 rows), 64B per row per split
    {
        const int row = tid;
        const uint32_t d = buf + 2 * ATILE + row * PITCH;
        const __half* s0 = bH + (size_t)row * strideB;
        const __half* s1 = bL + (size_t)row * strideB;
        cp16(d,          s0);      cp16(d + 16,          s0 + 8);
        cp16(d + 32,     s0 + 16); cp16(d + 48,          s0 + 24);
        cp16(d + BTILE,      s1);      cp16(d + BTILE + 16,  s1 + 8);
        cp16(d + BTILE + 32, s1 + 16); cp16(d + BTILE + 48,  s1 + 24);
    }
}

__device__ __forceinline__ void compute_chunk(
    uint32_t buf, int warpM, int warpN, int lid, float acc[2][16][4])
{
    const int arow = lid & 15, ka = (lid >> 4) & 1;
    const int g = lid >> 2, t = lid & 3;
    const uint32_t bbase = buf + 2 * ATILE + (warpN * 128 + g) * PITCH + t * 4;
    #pragma unroll
    for (int ks = 0; ks < 2; ks++) {
        uint32_t ahi[2][4], alo[2][4];
        #pragma unroll
        for (int mt = 0; mt < 2; mt++) {
            uint32_t ad = buf + (warpM*32 + mt*16 + arow) * PITCH + ks*32 + ka*16;
            LDM_X4(ahi[mt], ad);
            LDM_X4(alo[mt], ad + ATILE);
        }
        #pragma unroll
        for (int nt = 0; nt < 16; nt++) {
            uint32_t bd = bbase + nt * 8 * PITCH + ks * 32;
            uint32_t bh0, bh1, bl0, bl1;
            LDS32(bh0, bd);         LDS32(bh1, bd + 16);
            LDS32(bl0, bd + BTILE); LDS32(bl1, bd + BTILE + 16);
            MMA(acc[0][nt], ahi[0], bh0, bh1);   // hi*hi
            MMA(acc[1][nt], ahi[1], bh0, bh1);
            MMA(acc[0][nt], ahi[0], bl0, bl1);   // hi*lo
            MMA(acc[1][nt], ahi[1], bl0, bl1);
            MMA(acc[0][nt], alo[0], bh0, bh1);   // lo*hi
            MMA(acc[1][nt], alo[1], bh0, bh1);
        }
    }
}

// ---------------------------------------------------------------------------
// Stage 1: H[:, p*256:(p+1)*256] = tanh([Fi|Fj] @ W_pair[p] + b_pair[p])
// ---------------------------------------------------------------------------
__global__ __launch_bounds__(NTHREADS, 1)
void stage1_mma(const float* __restrict__ b_pair, const int* __restrict__ NAS)
{
    const int p = blockIdx.y;
    if (!pair_on(NAS, p)) return;
    const int rowBase = blockIdx.x * BM;

    extern __shared__ char smem[];
    const uint32_t sb = smem_u32(smem);
    const int tid = threadIdx.x, wid = tid >> 5, lid = tid & 31;
    const int warpM = wid & 3, warpN = wid >> 2;

    const __half* FiH = g_Fhi + (size_t)c_pi[p] * MROWS * EMBED + (size_t)rowBase * EMBED;
    const __half* FiL = g_Flo + (size_t)c_pi[p] * MROWS * EMBED + (size_t)rowBase * EMBED;
    const __half* FjH = g_Fhi + (size_t)c_pj[p] * MROWS * EMBED + (size_t)rowBase * EMBED;
    const __half* FjL = g_Flo + (size_t)c_pj[p] * MROWS * EMBED + (size_t)rowBase * EMBED;
    const __half* WH = g_Wpt_hi + (size_t)p * EMBED * KPAIR;
    const __half* WL = g_Wpt_lo + (size_t)p * EMBED * KPAIR;

    float acc[2][16][4];
    #pragma unroll
    for (int i = 0; i < 2; i++)
        #pragma unroll
        for (int j = 0; j < 16; j++)
            #pragma unroll
            for (int e = 0; e < 4; e++) acc[i][j][e] = 0.0f;

    const int NCH = KPAIR / KC;   // 16
    load_chunk_tiles(sb, tid, FiH, FiL, EMBED, WH, WL, KPAIR);
    CP_COMMIT();
    for (int c = 0; c < NCH; c++) {
        const int cur = c & 1;
        if (c + 1 < NCH) {
            const int k0 = (c + 1) * KC;
            const __half* aH = (k0 < EMBED) ? (FiH + k0) : (FjH + (k0 - EMBED));
            const __half* aL = (k0 < EMBED) ? (FiL + k0) : (FjL + (k0 - EMBED));
            load_chunk_tiles(sb + (1 - cur) * BUFBYTES, tid, aH, aL, EMBED,
                             WH + k0, WL + k0, KPAIR);
            CP_COMMIT();
            CP_WAIT(1);
        } else {
            CP_WAIT(0);
        }
        __syncthreads();
        compute_chunk(sb + cur * BUFBYTES, warpM, warpN, lid, acc);
        __syncthreads();
    }

    // epilogue: bias + tanh, split -> fp16 hi/lo, store H
    const int g = lid >> 2, t = lid & 3;
    #pragma unroll
    for (int mt = 0; mt < 2; mt++) {
        const int r0 = rowBase + warpM * 32 + mt * 16 + g;
        #pragma unroll
        for (int nt = 0; nt < 16; nt++) {
            const int colP = warpN * 128 + nt * 8 + 2 * t;
            const float b0 = __ldg(&b_pair[p * EMBED + colP]);
            const float b1 = __ldg(&b_pair[p * EMBED + colP + 1]);
            float v00 = tanhf(acc[mt][nt][0] + b0);
            float v01 = tanhf(acc[mt][nt][1] + b1);
            float v10 = tanhf(acc[mt][nt][2] + b0);
            float v11 = tanhf(acc[mt][nt][3] + b1);
            __half h0,l0,h1,l1;
            size_t o0 = (size_t)r0 * KFIN + (size_t)p * EMBED + colP;
            size_t o1 = o0 + (size_t)8 * KFIN;
            split_h(v00, h0, l0); split_h(v01, h1, l1);
            *reinterpret_cast<__half2*>(g_Hhi + o0) = __halves2half2(h0, h1);
            *reinterpret_cast<__half2*>(g_Hlo + o0) = __halves2half2(l0, l1);
            split_h(v10, h0, l0); split_h(v11, h1, l1);
            *reinterpret_cast<__half2*>(g_Hhi + o1) = __halves2half2(h0, h1);
            *reinterpret_cast<__half2*>(g_Hlo + o1) = __halves2half2(l0, l1);
        }
    }
}

// ---------------------------------------------------------------------------
// Stage 2: out = H @ W_final + b_final over active 256-wide K segments.
// ---------------------------------------------------------------------------
__global__ __launch_bounds__(NTHREADS, 1)
void stage2_mma(const float* __restrict__ b_final, const int* __restrict__ NAS,
                float* __restrict__ out)
{
    const int rowBase = blockIdx.x * BM;

    extern __shared__ char smem[];
    const uint32_t sb = smem_u32(smem);
    const int tid = threadIdx.x, wid = tid >> 5, lid = tid & 31;
    const int warpM = wid & 3, warpN = wid >> 2;

    int plist[PAIRS], nact = 0;
    #pragma unroll
    for (int p = 0; p < PAIRS; p++)
        if (pair_on(NAS, p)) plist[nact++] = p;
    const int NCH = nact * (EMBED / KC);   // nact * 8

    const __half* AH = g_Hhi + (size_t)rowBase * KFIN;
    const __half* AL = g_Hlo + (size_t)rowBase * KFIN;

    float acc[2][16][4];
    #pragma unroll
    for (int i = 0; i < 2; i++)
        #pragma unroll
        for (int j = 0; j < 16; j++)
            #pragma unroll
            for (int e = 0; e < 4; e++) acc[i][j][e] = 0.0f;

    {
        const int kcol = plist[0] * EMBED;
        load_chunk_tiles(sb, tid, AH + kcol, AL + kcol, KFIN,
                         g_Wft_hi + kcol, g_Wft_lo + kcol, KFIN);
        CP_COMMIT();
    }
    for (int c = 0; c < NCH; c++) {
        const int cur = c & 1;
        if (c + 1 < NCH) {
            const int i = c + 1;
            const int kcol = plist[i >> 3] * EMBED + (i & 7) * KC;
            load_chunk_tiles(sb + (1 - cur) * BUFBYTES, tid,
                             AH + kcol, AL + kcol, KFIN,
                             g_Wft_hi + kcol, g_Wft_lo + kcol, KFIN);
            CP_COMMIT();
            CP_WAIT(1);
        } else {
            CP_WAIT(0);
        }
        __syncthreads();
        compute_chunk(sb + cur * BUFBYTES, warpM, warpN, lid, acc);
        __syncthreads();
    }

    // epilogue: + b_final, fp32 out
    const int g = lid >> 2, t = lid & 3;
    #pragma unroll
    for (int mt = 0; mt < 2; mt++) {
        const int r0 = rowBase + warpM * 32 + mt * 16 + g;
        #pragma unroll
        for (int nt = 0; nt < 16; nt++) {
            const int colG = warpN * 128 + nt * 8 + 2 * t;
            const float b0 = __ldg(&b_final[colG]);
            const float b1 = __ldg(&b_final[colG + 1]);
            float2 w0 = make_float2(acc[mt][nt][0] + b0, acc[mt][nt][1] + b1);
            float2 w1 = make_float2(acc[mt][nt][2] + b0, acc[mt][nt][3] + b1);
            *reinterpret_cast<float2*>(out + (size_t)r0 * EMBED + colG)       = w0;
            *reinterpret_cast<float2*>(out + (size_t)(r0 + 8) * EMBED + colG) = w1;
        }
    }
}

extern "C" void kernel_launch(void* const* d_in, const int* in_sizes, int n_in,
                              void* d_out, int out_size)
{
    const float* features = (const float*)d_in[0];
    const float* W_pair   = (const float*)d_in[1];
    const float* b_pair   = (const float*)d_in[2];
    const float* W_final  = (const float*)d_in[3];
    const float* b_final  = (const float*)d_in[4];
    const int*   NAS      = (const int*)d_in[5];
    float* out = (float*)d_out;

    cudaFuncSetAttribute(stage1_mma, cudaFuncAttributeMaxDynamicSharedMemorySize, SMEM_BYTES);
    cudaFuncSetAttribute(stage2_mma, cudaFuncAttributeMaxDynamicSharedMemorySize, SMEM_BYTES);

    prep_feat  <<<dim3(4096, 6),   256>>>(features, NAS);
    prep_wpair <<<dim3(KPAIR/32, EMBED/32, PAIRS), dim3(32, 8)>>>(W_pair, NAS);
    prep_wfinal<<<dim3(KFIN/32,  EMBED/32),        dim3(32, 8)>>>(W_final, NAS);

    stage1_mma<<<dim3(MROWS/BM, PAIRS), NTHREADS, SMEM_BYTES>>>(b_pair, NAS);
    stage2_mma<<<dim3(MROWS/BM),        NTHREADS, SMEM_BYTES>>>(b_final, NAS, out);
}

// round 8
// speedup vs baseline: 3.6241x; 1.6316x over previous
#include <cuda_runtime.h>
#include <cuda_fp16.h>
#include <cstdint>
#include <math.h>

#define EMBED 256
#define PAIRS 15
#define MROWS 16384
#define KPAIR 512
#define KFIN  3840

#define BM 128
#define KC 32
#define NTHREADS 256
#define PITCH 80                           // smem row: 32 fp16 = 64B + 16B pad
#define ATILE (128 * PITCH)                // 10240 B
#define BTILE (256 * PITCH)                // 20480 B
#define BUFBYTES (2 * ATILE + BTILE)       // 40960 B  [Ahi][Alo][Bhi]
#define SMEM_BYTES (3 * BUFBYTES)          // 122880 B (triple buffered)

// ---- scratch (static device globals; allocation-guard-safe) ----
static __device__ __half g_Hhi[(size_t)MROWS * KFIN];
static __device__ __half g_Hlo[(size_t)MROWS * KFIN];
static __device__ __half g_Wpt[(size_t)PAIRS * EMBED * KPAIR];  // [p][n][k] fp16(hi)
static __device__ __half g_Wft[(size_t)EMBED * KFIN];           // [n][k]   fp16(hi)

__constant__ int c_pi[PAIRS] = {0,0,0,0,0,1,1,1,1,2,2,2,3,3,4};
__constant__ int c_pj[PAIRS] = {1,2,3,4,5,2,3,4,5,3,4,5,4,5,5};

__device__ __forceinline__ bool pair_on(const int* __restrict__ NAS, int p) {
    int i = c_pi[p], j = c_pj[p];
    int ni = (i < 2) ? 1 : __ldg(&NAS[i]);
    int nj = (j < 2) ? 1 : __ldg(&NAS[j]);
    return (ni != 0) && (nj != 0);
}
__device__ __forceinline__ void split_h(float x, __half& h, __half& l) {
    h = __float2half_rn(x);
    l = __float2half_rn(x - __half2float(h));
}
__device__ __forceinline__ uint32_t smem_u32(const void* p) {
    uint32_t a;
    asm("{ .reg .u64 t; cvta.to.shared.u64 t, %1; cvt.u32.u64 %0, t; }" : "=r"(a) : "l"(p));
    return a;
}

// ---- base-target PTX primitives (sm_80 baseline; valid on plain sm_103) ----
__device__ __forceinline__ void cp16(uint32_t dst, const void* src) {
    asm volatile("cp.async.cg.shared.global [%0], [%1], 16;" :: "r"(dst), "l"(src));
}
#define CP_COMMIT()      asm volatile("cp.async.commit_group;" ::: "memory")
#define CP_WAIT(n)       asm volatile("cp.async.wait_group %0;" :: "n"(n) : "memory")
#define LDM_X4(r, addr) \
    asm volatile("ldmatrix.sync.aligned.m8n8.x4.shared.b16 {%0,%1,%2,%3}, [%4];" \
        : "=r"((r)[0]), "=r"((r)[1]), "=r"((r)[2]), "=r"((r)[3]) : "r"(addr))
#define LDS32(v, addr) \
    asm volatile("ld.shared.b32 %0, [%1];" : "=r"(v) : "r"(addr))
#define MMA(d, a, b0, b1) \
    asm volatile("mma.sync.aligned.m16n8k16.row.col.f32.f16.f16.f32 " \
        "{%0,%1,%2,%3}, {%4,%5,%6,%7}, {%8,%9}, {%0,%1,%2,%3};" \
        : "+f"((d)[0]), "+f"((d)[1]), "+f"((d)[2]), "+f"((d)[3]) \
        : "r"((a)[0]), "r"((a)[1]), "r"((a)[2]), "r"((a)[3]), "r"(b0), "r"(b1))

// ---------------------------------------------------------------------------
// Prep: transpose weights to [n][k], fp16 (hi only).
// ---------------------------------------------------------------------------
__global__ void prep_wpair(const float* __restrict__ W_pair, const int* __restrict__ NAS) {
    int p = blockIdx.z;
    if (!pair_on(NAS, p)) return;
    __shared__ float tsh[32][33];
    int k0 = blockIdx.x * 32, n0 = blockIdx.y * 32;
    int tx = threadIdx.x, ty = threadIdx.y;
    const float* W = W_pair + (size_t)p * KPAIR * EMBED;
    #pragma unroll
    for (int i = 0; i < 4; i++)
        tsh[ty + i*8][tx] = W[(size_t)(k0 + ty + i*8) * EMBED + n0 + tx];
    __syncthreads();
    #pragma unroll
    for (int i = 0; i < 4; i++) {
        size_t o = ((size_t)p * EMBED + n0 + ty + i*8) * KPAIR + k0 + tx;
        g_Wpt[o] = __float2half_rn(tsh[tx][ty + i*8]);
    }
}

__global__ void prep_wfinal(const float* __restrict__ W_final, const int* __restrict__ NAS) {
    int k0 = blockIdx.x * 32;
    if (!pair_on(NAS, k0 >> 8)) return;
    __shared__ float tsh[32][33];
    int n0 = blockIdx.y * 32;
    int tx = threadIdx.x, ty = threadIdx.y;
    #pragma unroll
    for (int i = 0; i < 4; i++)
        tsh[ty + i*8][tx] = W_final[(size_t)(k0 + ty + i*8) * EMBED + n0 + tx];
    __syncthreads();
    #pragma unroll
    for (int i = 0; i < 4; i++) {
        size_t o = (size_t)(n0 + ty + i*8) * KFIN + k0 + tx;
        g_Wft[o] = __float2half_rn(tsh[tx][ty + i*8]);
    }
}

// ---------------------------------------------------------------------------
// Loaders
// ---------------------------------------------------------------------------
__device__ __forceinline__ void lda_regs(float4 r[4], const float* __restrict__ s) {
    r[0] = *reinterpret_cast<const float4*>(s);
    r[1] = *reinterpret_cast<const float4*>(s + 4);
    r[2] = *reinterpret_cast<const float4*>(s + 8);
    r[3] = *reinterpret_cast<const float4*>(s + 12);
}
__device__ __forceinline__ void split8(const float4 v0, const float4 v1, uint4& hi, uint4& lo) {
    float f[8] = {v0.x, v0.y, v0.z, v0.w, v1.x, v1.y, v1.z, v1.w};
    unsigned short h[8], l[8];
    #pragma unroll
    for (int q = 0; q < 8; q++) {
        __half hh, hl; split_h(f[q], hh, hl);
        h[q] = __half_as_ushort(hh); l[q] = __half_as_ushort(hl);
    }
    hi = make_uint4((uint32_t)h[0] | ((uint32_t)h[1] << 16), (uint32_t)h[2] | ((uint32_t)h[3] << 16),
                    (uint32_t)h[4] | ((uint32_t)h[5] << 16), (uint32_t)h[6] | ((uint32_t)h[7] << 16));
    lo = make_uint4((uint32_t)l[0] | ((uint32_t)l[1] << 16), (uint32_t)l[2] | ((uint32_t)l[3] << 16),
                    (uint32_t)l[4] | ((uint32_t)l[5] << 16), (uint32_t)l[6] | ((uint32_t)l[7] << 16));
}
// STS 16 fp32 values split into Ahi/Alo (stage 1 A path)
__device__ __forceinline__ void sts_split(char* smem, int bufofs, uint32_t dofs, const float4 r[4]) {
    uint4 h0, l0, h1, l1;
    split8(r[0], r[1], h0, l0);
    split8(r[2], r[3], h1, l1);
    char* d = smem + bufofs + dofs;
    *reinterpret_cast<uint4*>(d)              = h0;
    *reinterpret_cast<uint4*>(d + 16)         = h1;
    *reinterpret_cast<uint4*>(d + ATILE)      = l0;
    *reinterpret_cast<uint4*>(d + ATILE + 16) = l1;
}
// B tile: 256 rows x 32 halves, 1 thread/row
__device__ __forceinline__ void cp_b(uint32_t buf, int tid, const __half* bsrc, size_t stride) {
    const uint32_t d = buf + 2 * ATILE + tid * PITCH;
    const __half* s = bsrc + (size_t)tid * stride;
    cp16(d, s); cp16(d + 16, s + 8); cp16(d + 32, s + 16); cp16(d + 48, s + 24);
}
// stage-2 A tile: H hi/lo fp16, 2 threads/row
__device__ __forceinline__ void cp_a2(uint32_t buf, int tid, const __half* ah, const __half* al, size_t stride) {
    const int row = tid >> 1, h = tid & 1;
    const uint32_t d = buf + row * PITCH + h * 32;
    const __half* s0 = ah + (size_t)row * stride + h * 16;
    const __half* s1 = al + (size_t)row * stride + h * 16;
    cp16(d, s0);          cp16(d + 16, s0 + 8);
    cp16(d + ATILE, s1);  cp16(d + ATILE + 16, s1 + 8);
}

// ---------------------------------------------------------------------------
// Compute: 2 splits (Ahi*Bhi + Alo*Bhi), warp tile 32x128.
// ---------------------------------------------------------------------------
__device__ __forceinline__ void compute_chunk(
    uint32_t buf, int warpM, int warpN, int lid, float acc[2][16][4])
{
    const int arow = lid & 15, ka = (lid >> 4) & 1;
    const int g = lid >> 2, t = lid & 3;
    const uint32_t bbase = buf + 2 * ATILE + (warpN * 128 + g) * PITCH + t * 4;
    #pragma unroll
    for (int ks = 0; ks < 2; ks++) {
        uint32_t ahi[2][4], alo[2][4];
        #pragma unroll
        for (int mt = 0; mt < 2; mt++) {
            uint32_t ad = buf + (warpM*32 + mt*16 + arow) * PITCH + ks*32 + ka*16;
            LDM_X4(ahi[mt], ad);
            LDM_X4(alo[mt], ad + ATILE);
        }
        #pragma unroll
        for (int nt = 0; nt < 16; nt++) {
            uint32_t bd = bbase + nt * 8 * PITCH + ks * 32;
            uint32_t bh0, bh1;
            LDS32(bh0, bd); LDS32(bh1, bd + 16);
            MMA(acc[0][nt], ahi[0], bh0, bh1);
            MMA(acc[1][nt], ahi[1], bh0, bh1);
            MMA(acc[0][nt], alo[0], bh0, bh1);
            MMA(acc[1][nt], alo[1], bh0, bh1);
        }
    }
}

// ---------------------------------------------------------------------------
// Stage 1: H[:, p*256:(p+1)*256] = tanh([Fi|Fj] @ W_pair[p] + b_pair[p])
// Features loaded fp32 directly (no prep pass), split in-register.
// ---------------------------------------------------------------------------
__global__ __launch_bounds__(NTHREADS, 1)
void stage1_mma(const float* __restrict__ features,
                const float* __restrict__ b_pair, const int* __restrict__ NAS)
{
    const int p = blockIdx.y;
    if (!pair_on(NAS, p)) return;
    const int rowBase = blockIdx.x * BM;

    extern __shared__ char smem[];
    const uint32_t sb = smem_u32(smem);
    const int tid = threadIdx.x, wid = tid >> 5, lid = tid & 31;
    const int warpM = wid & 3, warpN = wid >> 2;

    const float* Fi = features + ((size_t)c_pi[p] * MROWS + rowBase) * EMBED;
    const float* Fj = features + ((size_t)c_pj[p] * MROWS + rowBase) * EMBED;
    const __half* WB = g_Wpt + (size_t)p * EMBED * KPAIR;

    const int arow = tid >> 1;
    const uint32_t adofs = arow * PITCH + (tid & 1) * 32;      // smem byte offset
    const size_t arofs = (size_t)arow * EMBED + (tid & 1) * 16; // gmem elem offset

    float acc[2][16][4];
    #pragma unroll
    for (int i = 0; i < 2; i++)
        #pragma unroll
        for (int j = 0; j < 16; j++)
            #pragma unroll
            for (int e = 0; e < 4; e++) acc[i][j][e] = 0.0f;

    const int NCH = KPAIR / KC;   // 16
    float4 rA[4];
    // prologue: chunk 0 (A direct), chunk 1 (A into regs), B0/B1 async
    lda_regs(rA, Fi + arofs);
    sts_split(smem, 0, adofs, rA);
    cp_b(sb, tid, WB, KPAIR); CP_COMMIT();
    lda_regs(rA, Fi + arofs + KC);
    cp_b(sb + BUFBYTES, tid, WB + KC, KPAIR); CP_COMMIT();

    for (int c = 0; c < NCH; c++) {
        if (c + 1 < NCH) sts_split(smem, ((c + 1) % 3) * BUFBYTES, adofs, rA);
        if (c + 2 < NCH) {
            const int k0 = (c + 2) * KC;
            const float* base = (k0 < EMBED) ? Fi : Fj;
            lda_regs(rA, base + arofs + (k0 & (EMBED - 1)));
        }
        if (c + 1 < NCH) { CP_WAIT(1); } else { CP_WAIT(0); }
        __syncthreads();
        if (c + 2 < NCH) {
            cp_b(sb + ((c + 2) % 3) * BUFBYTES, tid, WB + (c + 2) * KC, KPAIR);
            CP_COMMIT();
        }
        compute_chunk(sb + (c % 3) * BUFBYTES, warpM, warpN, lid, acc);
    }

    // epilogue: bias + tanh, split -> fp16 hi/lo, store H
    const int g = lid >> 2, t = lid & 3;
    #pragma unroll
    for (int mt = 0; mt < 2; mt++) {
        const int r0 = rowBase + warpM * 32 + mt * 16 + g;
        #pragma unroll
        for (int nt = 0; nt < 16; nt++) {
            const int colP = warpN * 128 + nt * 8 + 2 * t;
            const float b0 = __ldg(&b_pair[p * EMBED + colP]);
            const float b1 = __ldg(&b_pair[p * EMBED + colP + 1]);
            float v00 = tanhf(acc[mt][nt][0] + b0);
            float v01 = tanhf(acc[mt][nt][1] + b1);
            float v10 = tanhf(acc[mt][nt][2] + b0);
            float v11 = tanhf(acc[mt][nt][3] + b1);
            __half h0,l0,h1,l1;
            size_t o0 = (size_t)r0 * KFIN + (size_t)p * EMBED + colP;
            size_t o1 = o0 + (size_t)8 * KFIN;
            split_h(v00, h0, l0); split_h(v01, h1, l1);
            *reinterpret_cast<__half2*>(g_Hhi + o0) = __halves2half2(h0, h1);
            *reinterpret_cast<__half2*>(g_Hlo + o0) = __halves2half2(l0, l1);
            split_h(v10, h0, l0); split_h(v11, h1, l1);
            *reinterpret_cast<__half2*>(g_Hhi + o1) = __halves2half2(h0, h1);
            *reinterpret_cast<__half2*>(g_Hlo + o1) = __halves2half2(l0, l1);
        }
    }
}

// ---------------------------------------------------------------------------
// Stage 2: out = H @ W_final + b_final over active 256-wide K segments.
// ---------------------------------------------------------------------------
__global__ __launch_bounds__(NTHREADS, 1)
void stage2_mma(const float* __restrict__ b_final, const int* __restrict__ NAS,
                float* __restrict__ out)
{
    const int rowBase = blockIdx.x * BM;

    extern __shared__ char smem[];
    const uint32_t sb = smem_u32(smem);
    const int tid = threadIdx.x, wid = tid >> 5, lid = tid & 31;
    const int warpM = wid & 3, warpN = wid >> 2;

    int plist[PAIRS], nact = 0;
    #pragma unroll
    for (int p = 0; p < PAIRS; p++)
        if (pair_on(NAS, p)) plist[nact++] = p;
    const int NCH = nact * (EMBED / KC);   // nact * 8

    const __half* AH = g_Hhi + (size_t)rowBase * KFIN;
    const __half* AL = g_Hlo + (size_t)rowBase * KFIN;

    float acc[2][16][4];
    #pragma unroll
    for (int i = 0; i < 2; i++)
        #pragma unroll
        for (int j = 0; j < 16; j++)
            #pragma unroll
            for (int e = 0; e < 4; e++) acc[i][j][e] = 0.0f;

    // prologue: chunks 0,1
    {
        const int k0 = plist[0] * EMBED;
        cp_a2(sb, tid, AH + k0, AL + k0, KFIN);
        cp_b(sb, tid, g_Wft + k0, KFIN); CP_COMMIT();
        const int k1 = plist[1 >> 3] * EMBED + (1 & 7) * KC;
        cp_a2(sb + BUFBYTES, tid, AH + k1, AL + k1, KFIN);
        cp_b(sb + BUFBYTES, tid, g_Wft + k1, KFIN); CP_COMMIT();
    }
    for (int c = 0; c < NCH; c++) {
        if (c + 1 < NCH) { CP_WAIT(1); } else { CP_WAIT(0); }
        __syncthreads();
        if (c + 2 < NCH) {
            const int i = c + 2;
            const int kcol = plist[i >> 3] * EMBED + (i & 7) * KC;
            const uint32_t buf = sb + (i % 3) * BUFBYTES;
            cp_a2(buf, tid, AH + kcol, AL + kcol, KFIN);
            cp_b(buf, tid, g_Wft + kcol, KFIN);
            CP_COMMIT();
        }
        compute_chunk(sb + (c % 3) * BUFBYTES, warpM, warpN, lid, acc);
    }

    // epilogue: + b_final, fp32 out
    const int g = lid >> 2, t = lid & 3;
    #pragma unroll
    for (int mt = 0; mt < 2; mt++) {
        const int r0 = rowBase + warpM * 32 + mt * 16 + g;
        #pragma unroll
        for (int nt = 0; nt < 16; nt++) {
            const int colG = warpN * 128 + nt * 8 + 2 * t;
            const float b0 = __ldg(&b_final[colG]);
            const float b1 = __ldg(&b_final[colG + 1]);
            float2 w0 = make_float2(acc[mt][nt][0] + b0, acc[mt][nt][1] + b1);
            float2 w1 = make_float2(acc[mt][nt][2] + b0, acc[mt][nt][3] + b1);
            *reinterpret_cast<float2*>(out + (size_t)r0 * EMBED + colG)       = w0;
            *reinterpret_cast<float2*>(out + (size_t)(r0 + 8) * EMBED + colG) = w1;
        }
    }
}

extern "C" void kernel_launch(void* const* d_in, const int* in_sizes, int n_in,
                              void* d_out, int out_size)
{
    const float* features = (const float*)d_in[0];
    const float* W_pair   = (const float*)d_in[1];
    const float* b_pair   = (const float*)d_in[2];
    const float* W_final  = (const float*)d_in[3];
    const float* b_final  = (const float*)d_in[4];
    const int*   NAS      = (const int*)d_in[5];
    float* out = (float*)d_out;

    cudaFuncSetAttribute(stage1_mma, cudaFuncAttributeMaxDynamicSharedMemorySize, SMEM_BYTES);
    cudaFuncSetAttribute(stage2_mma, cudaFuncAttributeMaxDynamicSharedMemorySize, SMEM_BYTES);

    prep_wpair <<<dim3(KPAIR/32, EMBED/32, PAIRS), dim3(32, 8)>>>(W_pair, NAS);
    prep_wfinal<<<dim3(KFIN/32,  EMBED/32),        dim3(32, 8)>>>(W_final, NAS);

    stage1_mma<<<dim3(MROWS/BM, PAIRS), NTHREADS, SMEM_BYTES>>>(features, b_pair, NAS);
    stage2_mma<<<dim3(MROWS/BM),        NTHREADS, SMEM_BYTES>>>(b_final, NAS, out);
}

// round 9
// speedup vs baseline: 3.6257x; 1.0004x over previous
#include <cuda_runtime.h>
#include <cuda_fp16.h>
#include <cstdint>
#include <math.h>

#define EMBED 256
#define PAIRS 15
#define MROWS 16384
#define KPAIR 512
#define KFIN  3840

#define BM 64
#define KC 32
#define NTHREADS 256
#define PITCH 80                          // A/B smem row: 32 fp16 = 64B + 16B pad
#define ATILE (64 * PITCH)                // 5120 B
#define BTILE (256 * PITCH)               // 20480 B
#define BUFB  (2 * ATILE + BTILE)         // 30720 B  [Ahi][Alo][B]
#define HPITCH 528                        // 64-row H tile: 256 fp16 + 16B pad
#define HOFF  (3 * BUFB)                  // 92160
#define SMEM_BYTES (HOFF + 64 * HPITCH)   // 125952

// ---- scratch (static device globals; allocation-guard-safe) ----
static __device__ __half g_Wpt[(size_t)PAIRS * EMBED * KPAIR];  // [p][n][k] fp16
static __device__ __half g_Wft[(size_t)EMBED * KFIN];           // [n][k]   fp16

__constant__ int c_pi[PAIRS] = {0,0,0,0,0,1,1,1,1,2,2,2,3,3,4};
__constant__ int c_pj[PAIRS] = {1,2,3,4,5,2,3,4,5,3,4,5,4,5,5};

__device__ __forceinline__ bool pair_on(const int* __restrict__ NAS, int p) {
    int i = c_pi[p], j = c_pj[p];
    int ni = (i < 2) ? 1 : __ldg(&NAS[i]);
    int nj = (j < 2) ? 1 : __ldg(&NAS[j]);
    return (ni != 0) && (nj != 0);
}
__device__ __forceinline__ void split_h(float x, __half& h, __half& l) {
    h = __float2half_rn(x);
    l = __float2half_rn(x - __half2float(h));
}
__device__ __forceinline__ uint32_t smem_u32(const void* p) {
    uint32_t a;
    asm("{ .reg .u64 t; cvta.to.shared.u64 t, %1; cvt.u32.u64 %0, t; }" : "=r"(a) : "l"(p));
    return a;
}

// ---- base-target PTX primitives (sm_80 baseline; valid on plain sm_103) ----
__device__ __forceinline__ void cp16(uint32_t dst, const void* src) {
    asm volatile("cp.async.cg.shared.global [%0], [%1], 16;" :: "r"(dst), "l"(src));
}
#define CP_COMMIT()      asm volatile("cp.async.commit_group;" ::: "memory")
#define CP_WAIT(n)       asm volatile("cp.async.wait_group %0;" :: "n"(n) : "memory")
#define LDM_X4(r, addr) \
    asm volatile("ldmatrix.sync.aligned.m8n8.x4.shared.b16 {%0,%1,%2,%3}, [%4];" \
        : "=r"((r)[0]), "=r"((r)[1]), "=r"((r)[2]), "=r"((r)[3]) : "r"(addr))
#define LDS32(v, addr) \
    asm volatile("ld.shared.b32 %0, [%1];" : "=r"(v) : "r"(addr))
#define MMA(d, a, b0, b1) \
    asm volatile("mma.sync.aligned.m16n8k16.row.col.f32.f16.f16.f32 " \
        "{%0,%1,%2,%3}, {%4,%5,%6,%7}, {%8,%9}, {%0,%1,%2,%3};" \
        : "+f"((d)[0]), "+f"((d)[1]), "+f"((d)[2]), "+f"((d)[3]) \
        : "r"((a)[0]), "r"((a)[1]), "r"((a)[2]), "r"((a)[3]), "r"(b0), "r"(b1))

// ---------------------------------------------------------------------------
// Prep: transpose weights to [n][k], fp16.
// ---------------------------------------------------------------------------
__global__ void prep_wpair(const float* __restrict__ W_pair, const int* __restrict__ NAS) {
    int p = blockIdx.z;
    if (!pair_on(NAS, p)) return;
    __shared__ float tsh[32][33];
    int k0 = blockIdx.x * 32, n0 = blockIdx.y * 32;
    int tx = threadIdx.x, ty = threadIdx.y;
    const float* W = W_pair + (size_t)p * KPAIR * EMBED;
    #pragma unroll
    for (int i = 0; i < 4; i++)
        tsh[ty + i*8][tx] = W[(size_t)(k0 + ty + i*8) * EMBED + n0 + tx];
    __syncthreads();
    #pragma unroll
    for (int i = 0; i < 4; i++) {
        size_t o = ((size_t)p * EMBED + n0 + ty + i*8) * KPAIR + k0 + tx;
        g_Wpt[o] = __float2half_rn(tsh[tx][ty + i*8]);
    }
}

__global__ void prep_wfinal(const float* __restrict__ W_final, const int* __restrict__ NAS) {
    int k0 = blockIdx.x * 32;
    if (!pair_on(NAS, k0 >> 8)) return;
    __shared__ float tsh[32][33];
    int n0 = blockIdx.y * 32;
    int tx = threadIdx.x, ty = threadIdx.y;
    #pragma unroll
    for (int i = 0; i < 4; i++)
        tsh[ty + i*8][tx] = W_final[(size_t)(k0 + ty + i*8) * EMBED + n0 + tx];
    __syncthreads();
    #pragma unroll
    for (int i = 0; i < 4; i++) {
        size_t o = (size_t)(n0 + ty + i*8) * KFIN + k0 + tx;
        g_Wft[o] = __float2half_rn(tsh[tx][ty + i*8]);
    }
}

// ---------------------------------------------------------------------------
// Loaders
// ---------------------------------------------------------------------------
// A (stage-1): 64 rows x 32 k fp32 -> hi/lo fp16. row = tid&63, q = tid>>6
// (conflict-free STS: bank walk 20r mod 32 distinct within octet).
__device__ __forceinline__ void lda_regs(float4 r[2], const float* __restrict__ s) {
    r[0] = *reinterpret_cast<const float4*>(s);
    r[1] = *reinterpret_cast<const float4*>(s + 4);
}
__device__ __forceinline__ void sts_split(char* smem, int bufofs, uint32_t dofs,
                                          const float4 r[2]) {
    float f[8] = {r[0].x, r[0].y, r[0].z, r[0].w, r[1].x, r[1].y, r[1].z, r[1].w};
    unsigned short h[8], l[8];
    #pragma unroll
    for (int q = 0; q < 8; q++) {
        __half hh, hl; split_h(f[q], hh, hl);
        h[q] = __half_as_ushort(hh); l[q] = __half_as_ushort(hl);
    }
    char* d = smem + bufofs + dofs;
    *reinterpret_cast<uint4*>(d) =
        make_uint4((uint32_t)h[0] | ((uint32_t)h[1] << 16), (uint32_t)h[2] | ((uint32_t)h[3] << 16),
                   (uint32_t)h[4] | ((uint32_t)h[5] << 16), (uint32_t)h[6] | ((uint32_t)h[7] << 16));
    *reinterpret_cast<uint4*>(d + ATILE) =
        make_uint4((uint32_t)l[0] | ((uint32_t)l[1] << 16), (uint32_t)l[2] | ((uint32_t)l[3] << 16),
                   (uint32_t)l[4] | ((uint32_t)l[5] << 16), (uint32_t)l[6] | ((uint32_t)l[7] << 16));
}
// B tile: 256 rows(n) x 32 k fp16, 1 thread/row.
__device__ __forceinline__ void cp_b(uint32_t buf, int tid, const __half* bsrc, size_t stride) {
    const uint32_t d = buf + 2 * ATILE + tid * PITCH;
    const __half* s = bsrc + (size_t)tid * stride;
    cp16(d, s); cp16(d + 16, s + 8); cp16(d + 32, s + 16); cp16(d + 48, s + 24);
}

// ---------------------------------------------------------------------------
// Compute. 8 warps: warpM = wid&1 (32 rows), warpN = wid>>1 (64 cols).
// ---------------------------------------------------------------------------
__device__ __forceinline__ void compute1(uint32_t buf, int warpM, int warpN,
                                         int lid, float acc[2][8][4]) {
    const int arow = lid & 15, ka = (lid >> 4) & 1;
    const int g = lid >> 2, t = lid & 3;
    const uint32_t bbase = buf + 2 * ATILE + (warpN * 64 + g) * PITCH + t * 4;
    #pragma unroll
    for (int ks = 0; ks < 2; ks++) {
        uint32_t ahi[2][4], alo[2][4];
        #pragma unroll
        for (int mt = 0; mt < 2; mt++) {
            uint32_t ad = buf + (warpM*32 + mt*16 + arow) * PITCH + ks*32 + ka*16;
            LDM_X4(ahi[mt], ad);
            LDM_X4(alo[mt], ad + ATILE);
        }
        #pragma unroll
        for (int nt = 0; nt < 8; nt++) {
            uint32_t bd = bbase + nt * 8 * PITCH + ks * 32;
            uint32_t b0, b1;
            LDS32(b0, bd); LDS32(b1, bd + 16);
            MMA(acc[0][nt], ahi[0], b0, b1);
            MMA(acc[1][nt], ahi[1], b0, b1);
            MMA(acc[0][nt], alo[0], b0, b1);
            MMA(acc[1][nt], alo[1], b0, b1);
        }
    }
}
// GEMM2: A = H in smem (fp16, single split), B in chunk buffer.
__device__ __forceinline__ void compute2(uint32_t buf, uint32_t hbase, int c2,
                                         int warpM, int warpN, int lid, float acc[2][8][4]) {
    const int arow = lid & 15, ka = (lid >> 4) & 1;
    const int g = lid >> 2, t = lid & 3;
    const uint32_t bbase = buf + 2 * ATILE + (warpN * 64 + g) * PITCH + t * 4;
    #pragma unroll
    for (int ks = 0; ks < 2; ks++) {
        uint32_t a[2][4];
        #pragma unroll
        for (int mt = 0; mt < 2; mt++) {
            uint32_t ad = hbase + (warpM*32 + mt*16 + arow) * HPITCH
                        + c2*64 + ks*32 + ka*16;
            LDM_X4(a[mt], ad);
        }
        #pragma unroll
        for (int nt = 0; nt < 8; nt++) {
            uint32_t bd = bbase + nt * 8 * PITCH + ks * 32;
            uint32_t b0, b1;
            LDS32(b0, bd); LDS32(b1, bd + 16);
            MMA(acc[0][nt], a[0], b0, b1);
            MMA(acc[1][nt], a[1], b0, b1);
        }
    }
}

// ---------------------------------------------------------------------------
// Fused kernel: per 64-row block, loop active pairs:
//   H = tanh([Fi|Fj] @ Wp + bp) (smem)  ;  out_acc += H @ Wft[p]
// ---------------------------------------------------------------------------
__global__ __launch_bounds__(NTHREADS, 1)
void fused_mma(const float* __restrict__ features,
               const float* __restrict__ b_pair,
               const float* __restrict__ b_final,
               const int*   __restrict__ NAS,
               float*       __restrict__ out)
{
    const int rowBase = blockIdx.x * BM;
    extern __shared__ char smem[];
    const uint32_t sb = smem_u32(smem);
    const uint32_t hbase = sb + HOFF;
    const int tid = threadIdx.x, wid = tid >> 5, lid = tid & 31;
    const int warpM = wid & 1, warpN = wid >> 1;
    const int g = lid >> 2, t = lid & 3;

    // A-loader lane mapping (conflict-free)
    const int arow = tid & 63, aq = tid >> 6;
    const uint32_t adofs = arow * PITCH + aq * 16;             // smem bytes
    const size_t   arofs = (size_t)arow * EMBED + aq * 8;      // gmem elems

    int plist[PAIRS], nact = 0;
    #pragma unroll
    for (int p = 0; p < PAIRS; p++)
        if (pair_on(NAS, p)) plist[nact++] = p;

    float acc2[2][8][4];
    #pragma unroll
    for (int i = 0; i < 2; i++)
        #pragma unroll
        for (int j = 0; j < 8; j++)
            #pragma unroll
            for (int e = 0; e < 4; e++) acc2[i][j][e] = 0.0f;

    for (int pi = 0; pi < nact; pi++) {
        const int p = plist[pi];
        const float* Fi = features + ((size_t)c_pi[p] * MROWS + rowBase) * EMBED;
        const float* Fj = features + ((size_t)c_pj[p] * MROWS + rowBase) * EMBED;
        const __half* WB = g_Wpt + (size_t)p * EMBED * KPAIR;

        float acc1[2][8][4];
        #pragma unroll
        for (int i = 0; i < 2; i++)
            #pragma unroll
            for (int j = 0; j < 8; j++)
                #pragma unroll
                for (int e = 0; e < 4; e++) acc1[i][j][e] = 0.0f;

        // ---- GEMM1: 16 chunks over K=512, triple-buffered ----
        const int NCH1 = KPAIR / KC;
        float4 rA[2];
        lda_regs(rA, Fi + arofs);
        sts_split(smem, 0, adofs, rA);
        cp_b(sb, tid, WB, KPAIR); CP_COMMIT();
        lda_regs(rA, Fi + arofs + KC);
        cp_b(sb + BUFB, tid, WB + KC, KPAIR); CP_COMMIT();

        for (int c = 0; c < NCH1; c++) {
            if (c + 1 < NCH1) sts_split(smem, ((c + 1) % 3) * BUFB, adofs, rA);
            if (c + 2 < NCH1) {
                const int k0 = (c + 2) * KC;
                const float* base = (k0 < EMBED) ? Fi : Fj;
                lda_regs(rA, base + arofs + (k0 & (EMBED - 1)));
            }
            if (c + 1 < NCH1) { CP_WAIT(1); } else { CP_WAIT(0); }
            __syncthreads();
            if (c + 2 < NCH1) {
                cp_b(sb + ((c + 2) % 3) * BUFB, tid, WB + (c + 2) * KC, KPAIR);
                CP_COMMIT();
            }
            compute1(sb + (c % 3) * BUFB, warpM, warpN, lid, acc1);
        }

        // ---- H epilogue: bias + tanh -> fp16 into smem H ----
        #pragma unroll
        for (int mt = 0; mt < 2; mt++) {
            const int r0 = warpM * 32 + mt * 16 + g;
            char* hrow0 = smem + HOFF + (size_t)r0 * HPITCH;
            char* hrow1 = hrow0 + 8 * HPITCH;
            #pragma unroll
            for (int nt = 0; nt < 8; nt++) {
                const int colP = warpN * 64 + nt * 8 + 2 * t;
                const float b0 = __ldg(&b_pair[p * EMBED + colP]);
                const float b1 = __ldg(&b_pair[p * EMBED + colP + 1]);
                *reinterpret_cast<__half2*>(hrow0 + colP * 2) =
                    __floats2half2_rn(tanhf(acc1[mt][nt][0] + b0), tanhf(acc1[mt][nt][1] + b1));
                *reinterpret_cast<__half2*>(hrow1 + colP * 2) =
                    __floats2half2_rn(tanhf(acc1[mt][nt][2] + b0), tanhf(acc1[mt][nt][3] + b1));
            }
        }
        __syncthreads();   // H visible to all warps; chunk buffers free

        // ---- GEMM2: 8 chunks over this pair's 256-wide K segment ----
        const __half* WF = g_Wft + (size_t)p * EMBED;  // column offset p*256 in [n][k]
        cp_b(sb, tid, WF, KFIN); CP_COMMIT();
        cp_b(sb + BUFB, tid, WF + KC, KFIN); CP_COMMIT();
        const int NCH2 = EMBED / KC;
        for (int c = 0; c < NCH2; c++) {
            if (c + 1 < NCH2) { CP_WAIT(1); } else { CP_WAIT(0); }
            __syncthreads();
            if (c + 2 < NCH2) {
                cp_b(sb + ((c + 2) % 3) * BUFB, tid, WF + (c + 2) * KC, KFIN);
                CP_COMMIT();
            }
            compute2(sb + (c % 3) * BUFB, hbase, c, warpM, warpN, lid, acc2);
        }
        __syncthreads();   // all buffers/H free before next pair
    }

    // ---- final epilogue: + b_final, fp32 out ----
    #pragma unroll
    for (int mt = 0; mt < 2; mt++) {
        const int r0 = rowBase + warpM * 32 + mt * 16 + g;
        #pragma unroll
        for (int nt = 0; nt < 8; nt++) {
            const int colG = warpN * 64 + nt * 8 + 2 * t;
            const float b0 = __ldg(&b_final[colG]);
            const float b1 = __ldg(&b_final[colG + 1]);
            float2 w0 = make_float2(acc2[0 * 2 + 0 ? 0 : 0][nt][0], 0.0f); // placeholder avoided below
            (void)w0;
            float2 v0 = make_float2(acc2[mt][nt][0] + b0, acc2[mt][nt][1] + b1);
            float2 v1 = make_float2(acc2[mt][nt][2] + b0, acc2[mt][nt][3] + b1);
            *reinterpret_cast<float2*>(out + (size_t)r0 * EMBED + colG)       = v0;
            *reinterpret_cast<float2*>(out + (size_t)(r0 + 8) * EMBED + colG) = v1;
        }
    }
}

extern "C" void kernel_launch(void* const* d_in, const int* in_sizes, int n_in,
                              void* d_out, int out_size)
{
    const float* features = (const float*)d_in[0];
    const float* W_pair   = (const float*)d_in[1];
    const float* b_pair   = (const float*)d_in[2];
    const float* W_final  = (const float*)d_in[3];
    const float* b_final  = (const float*)d_in[4];
    const int*   NAS      = (const int*)d_in[5];
    float* out = (float*)d_out;

    cudaFuncSetAttribute(fused_mma, cudaFuncAttributeMaxDynamicSharedMemorySize, SMEM_BYTES);

    prep_wpair <<<dim3(KPAIR/32, EMBED/32, PAIRS), dim3(32, 8)>>>(W_pair, NAS);
    prep_wfinal<<<dim3(KFIN/32,  EMBED/32),        dim3(32, 8)>>>(W_final, NAS);

    fused_mma<<<dim3(MROWS/BM), NTHREADS, SMEM_BYTES>>>(features, b_pair, b_final, NAS, out);
}

// round 10
// speedup vs baseline: 3.8295x; 1.0562x over previous
#include <cuda_runtime.h>
#include <cuda_fp16.h>
#include <cstdint>
#include <math.h>

#define EMBED 256
#define PAIRS 15
#define MROWS 16384
#define KPAIR 512
#define KFIN  3840

#define BM 64
#define KC 32
#define NTHREADS 512
#define PITCH 80                          // A/B smem row: 32 fp16 = 64B + 16B pad
#define ATILE (64 * PITCH)                // 5120 B
#define BTILE (256 * PITCH)               // 20480 B
#define BUFB  (2 * ATILE + BTILE)         // 30720 B  [Ahi][Alo][B]
#define HPITCH 528                        // 64-row H tile: 256 fp16 + 16B pad
#define HOFF  (3 * BUFB)                  // 92160
#define SMEM_BYTES (HOFF + 64 * HPITCH)   // 125952

// ---- scratch (static device globals; allocation-guard-safe) ----
static __device__ __half g_Wpt[(size_t)PAIRS * EMBED * KPAIR];  // [p][n][k] fp16
static __device__ __half g_Wft[(size_t)EMBED * KFIN];           // [n][k]   fp16

__constant__ int c_pi[PAIRS] = {0,0,0,0,0,1,1,1,1,2,2,2,3,3,4};
__constant__ int c_pj[PAIRS] = {1,2,3,4,5,2,3,4,5,3,4,5,4,5,5};

__device__ __forceinline__ bool pair_on(const int* __restrict__ NAS, int p) {
    int i = c_pi[p], j = c_pj[p];
    int ni = (i < 2) ? 1 : __ldg(&NAS[i]);
    int nj = (j < 2) ? 1 : __ldg(&NAS[j]);
    return (ni != 0) && (nj != 0);
}
__device__ __forceinline__ void split_h(float x, __half& h, __half& l) {
    h = __float2half_rn(x);
    l = __float2half_rn(x - __half2float(h));
}
__device__ __forceinline__ uint32_t smem_u32(const void* p) {
    uint32_t a;
    asm("{ .reg .u64 t; cvta.to.shared.u64 t, %1; cvt.u32.u64 %0, t; }" : "=r"(a) : "l"(p));
    return a;
}

// ---- base-target PTX primitives (sm_80 baseline; valid on plain sm_103) ----
__device__ __forceinline__ void cp16(uint32_t dst, const void* src) {
    asm volatile("cp.async.cg.shared.global [%0], [%1], 16;" :: "r"(dst), "l"(src));
}
#define CP_COMMIT()      asm volatile("cp.async.commit_group;" ::: "memory")
#define CP_WAIT(n)       asm volatile("cp.async.wait_group %0;" :: "n"(n) : "memory")
#define LDM_X4(r, addr) \
    asm volatile("ldmatrix.sync.aligned.m8n8.x4.shared.b16 {%0,%1,%2,%3}, [%4];" \
        : "=r"((r)[0]), "=r"((r)[1]), "=r"((r)[2]), "=r"((r)[3]) : "r"(addr))
#define LDS32(v, addr) \
    asm volatile("ld.shared.b32 %0, [%1];" : "=r"(v) : "r"(addr))
#define MMA(d, a, b0, b1) \
    asm volatile("mma.sync.aligned.m16n8k16.row.col.f32.f16.f16.f32 " \
        "{%0,%1,%2,%3}, {%4,%5,%6,%7}, {%8,%9}, {%0,%1,%2,%3};" \
        : "+f"((d)[0]), "+f"((d)[1]), "+f"((d)[2]), "+f"((d)[3]) \
        : "r"((a)[0]), "r"((a)[1]), "r"((a)[2]), "r"((a)[3]), "r"(b0), "r"(b1))

// ---------------------------------------------------------------------------
// Prep: transpose weights to [n][k], fp16.
// ---------------------------------------------------------------------------
__global__ void prep_wpair(const float* __restrict__ W_pair, const int* __restrict__ NAS) {
    int p = blockIdx.z;
    if (!pair_on(NAS, p)) return;
    __shared__ float tsh[32][33];
    int k0 = blockIdx.x * 32, n0 = blockIdx.y * 32;
    int tx = threadIdx.x, ty = threadIdx.y;
    const float* W = W_pair + (size_t)p * KPAIR * EMBED;
    #pragma unroll
    for (int i = 0; i < 4; i++)
        tsh[ty + i*8][tx] = W[(size_t)(k0 + ty + i*8) * EMBED + n0 + tx];
    __syncthreads();
    #pragma unroll
    for (int i = 0; i < 4; i++) {
        size_t o = ((size_t)p * EMBED + n0 + ty + i*8) * KPAIR + k0 + tx;
        g_Wpt[o] = __float2half_rn(tsh[tx][ty + i*8]);
    }
}

__global__ void prep_wfinal(const float* __restrict__ W_final, const int* __restrict__ NAS) {
    int k0 = blockIdx.x * 32;
    if (!pair_on(NAS, k0 >> 8)) return;
    __shared__ float tsh[32][33];
    int n0 = blockIdx.y * 32;
    int tx = threadIdx.x, ty = threadIdx.y;
    #pragma unroll
    for (int i = 0; i < 4; i++)
        tsh[ty + i*8][tx] = W_final[(size_t)(k0 + ty + i*8) * EMBED + n0 + tx];
    __syncthreads();
    #pragma unroll
    for (int i = 0; i < 4; i++) {
        size_t o = (size_t)(n0 + ty + i*8) * KFIN + k0 + tx;
        g_Wft[o] = __float2half_rn(tsh[tx][ty + i*8]);
    }
}

// ---------------------------------------------------------------------------
// Loaders
// ---------------------------------------------------------------------------
__device__ __forceinline__ void lda_regs(float4 r[2], const float* __restrict__ s) {
    r[0] = *reinterpret_cast<const float4*>(s);
    r[1] = *reinterpret_cast<const float4*>(s + 4);
}
// A (GEMM1): 64 rows x 32 k fp32 -> hi/lo fp16; threads 0..255 (4/row x 8 elems).
__device__ __forceinline__ void sts_split(char* smem, int bufofs, uint32_t dofs,
                                          const float4 r[2]) {
    float f[8] = {r[0].x, r[0].y, r[0].z, r[0].w, r[1].x, r[1].y, r[1].z, r[1].w};
    unsigned short h[8], l[8];
    #pragma unroll
    for (int q = 0; q < 8; q++) {
        __half hh, hl; split_h(f[q], hh, hl);
        h[q] = __half_as_ushort(hh); l[q] = __half_as_ushort(hl);
    }
    char* d = smem + bufofs + dofs;
    *reinterpret_cast<uint4*>(d) =
        make_uint4((uint32_t)h[0] | ((uint32_t)h[1] << 16), (uint32_t)h[2] | ((uint32_t)h[3] << 16),
                   (uint32_t)h[4] | ((uint32_t)h[5] << 16), (uint32_t)h[6] | ((uint32_t)h[7] << 16));
    *reinterpret_cast<uint4*>(d + ATILE) =
        make_uint4((uint32_t)l[0] | ((uint32_t)l[1] << 16), (uint32_t)l[2] | ((uint32_t)l[3] << 16),
                   (uint32_t)l[4] | ((uint32_t)l[5] << 16), (uint32_t)l[6] | ((uint32_t)l[7] << 16));
}
// B tile: 256 rows(n) x 32 k fp16, 2 threads/row (512 threads).
__device__ __forceinline__ void cp_b(uint32_t buf, int tid, const __half* bsrc, size_t stride) {
    const int row = tid >> 1, h = tid & 1;
    const uint32_t d = buf + 2 * ATILE + row * PITCH + h * 32;
    const __half* s = bsrc + (size_t)row * stride + h * 16;
    cp16(d, s); cp16(d + 16, s + 8);
}

// ---------------------------------------------------------------------------
// Compute. 16 warps: warpM = wid&1 (32 rows), warpN = wid>>1 (32 cols of 256).
// ---------------------------------------------------------------------------
__device__ __forceinline__ void compute1(uint32_t buf, int warpM, int warpN,
                                         int lid, float acc[2][4][4]) {
    const int arow = lid & 15, ka = (lid >> 4) & 1;
    const int g = lid >> 2, t = lid & 3;
    const uint32_t bbase = buf + 2 * ATILE + (warpN * 32 + g) * PITCH + t * 4;
    #pragma unroll
    for (int ks = 0; ks < 2; ks++) {
        uint32_t ahi[2][4], alo[2][4];
        #pragma unroll
        for (int mt = 0; mt < 2; mt++) {
            uint32_t ad = buf + (warpM*32 + mt*16 + arow) * PITCH + ks*32 + ka*16;
            LDM_X4(ahi[mt], ad);
            LDM_X4(alo[mt], ad + ATILE);
        }
        #pragma unroll
        for (int nt = 0; nt < 4; nt++) {
            uint32_t bd = bbase + nt * 8 * PITCH + ks * 32;
            uint32_t b0, b1;
            LDS32(b0, bd); LDS32(b1, bd + 16);
            MMA(acc[0][nt], ahi[0], b0, b1);
            MMA(acc[1][nt], ahi[1], b0, b1);
            MMA(acc[0][nt], alo[0], b0, b1);
            MMA(acc[1][nt], alo[1], b0, b1);
        }
    }
}
// GEMM2: A = H in smem (fp16, single), B in chunk buffer.
__device__ __forceinline__ void compute2(uint32_t buf, uint32_t hbase, int c2,
                                         int warpM, int warpN, int lid, float acc[2][4][4]) {
    const int arow = lid & 15, ka = (lid >> 4) & 1;
    const int g = lid >> 2, t = lid & 3;
    const uint32_t bbase = buf + 2 * ATILE + (warpN * 32 + g) * PITCH + t * 4;
    #pragma unroll
    for (int ks = 0; ks < 2; ks++) {
        uint32_t a[2][4];
        #pragma unroll
        for (int mt = 0; mt < 2; mt++) {
            uint32_t ad = hbase + (warpM*32 + mt*16 + arow) * HPITCH
                        + c2*64 + ks*32 + ka*16;
            LDM_X4(a[mt], ad);
        }
        #pragma unroll
        for (int nt = 0; nt < 4; nt++) {
            uint32_t bd = bbase + nt * 8 * PITCH + ks * 32;
            uint32_t b0, b1;
            LDS32(b0, bd); LDS32(b1, bd + 16);
            MMA(acc[0][nt], a[0], b0, b1);
            MMA(acc[1][nt], a[1], b0, b1);
        }
    }
}

// ---------------------------------------------------------------------------
// Fused kernel: per 64-row block, loop active pairs:
//   H = tanh([Fi|Fj] @ Wp + bp) (smem)  ;  out_acc += H @ Wft[p]
// ---------------------------------------------------------------------------
__global__ __launch_bounds__(NTHREADS, 1)
void fused_mma(const float* __restrict__ features,
               const float* __restrict__ b_pair,
               const float* __restrict__ b_final,
               const int*   __restrict__ NAS,
               float*       __restrict__ out)
{
    const int rowBase = blockIdx.x * BM;
    extern __shared__ char smem[];
    const uint32_t sb = smem_u32(smem);
    const uint32_t hbase = sb + HOFF;
    const int tid = threadIdx.x, wid = tid >> 5, lid = tid & 31;
    const int warpM = wid & 1, warpN = wid >> 1;
    const int g = lid >> 2, t = lid & 3;
    const bool aldr = (tid < 256);

    // A-loader lane mapping (threads 0..255; 4 threads/row x 8 fp32)
    const int arow = tid & 63, aq = (tid >> 6) & 3;
    const uint32_t adofs = arow * PITCH + aq * 16;             // smem bytes
    const size_t   arofs = (size_t)arow * EMBED + aq * 8;      // gmem elems

    int plist[PAIRS], nact = 0;
    #pragma unroll
    for (int p = 0; p < PAIRS; p++)
        if (pair_on(NAS, p)) plist[nact++] = p;

    float acc2[2][4][4];
    #pragma unroll
    for (int i = 0; i < 2; i++)
        #pragma unroll
        for (int j = 0; j < 4; j++)
            #pragma unroll
            for (int e = 0; e < 4; e++) acc2[i][j][e] = 0.0f;

    for (int pi = 0; pi < nact; pi++) {
        const int p = plist[pi];
        const float* Fi = features + ((size_t)c_pi[p] * MROWS + rowBase) * EMBED;
        const float* Fj = features + ((size_t)c_pj[p] * MROWS + rowBase) * EMBED;
        const __half* WB = g_Wpt + (size_t)p * EMBED * KPAIR;

        float acc1[2][4][4];
        #pragma unroll
        for (int i = 0; i < 2; i++)
            #pragma unroll
            for (int j = 0; j < 4; j++)
                #pragma unroll
                for (int e = 0; e < 4; e++) acc1[i][j][e] = 0.0f;

        // ---- GEMM1: 16 chunks over K=512, triple-buffered ----
        const int NCH1 = KPAIR / KC;
        float4 rA[2];
        if (aldr) {
            lda_regs(rA, Fi + arofs);
            sts_split(smem, 0, adofs, rA);
        }
        cp_b(sb, tid, WB, KPAIR); CP_COMMIT();
        if (aldr) lda_regs(rA, Fi + arofs + KC);
        cp_b(sb + BUFB, tid, WB + KC, KPAIR); CP_COMMIT();

        for (int c = 0; c < NCH1; c++) {
            if (aldr) {
                if (c + 1 < NCH1) sts_split(smem, ((c + 1) % 3) * BUFB, adofs, rA);
                if (c + 2 < NCH1) {
                    const int k0 = (c + 2) * KC;
                    const float* base = (k0 < EMBED) ? Fi : Fj;
                    lda_regs(rA, base + arofs + (k0 & (EMBED - 1)));
                }
            }
            if (c + 1 < NCH1) { CP_WAIT(1); } else { CP_WAIT(0); }
            __syncthreads();
            if (c + 2 < NCH1) {
                cp_b(sb + ((c + 2) % 3) * BUFB, tid, WB + (c + 2) * KC, KPAIR);
                CP_COMMIT();
            }
            compute1(sb + (c % 3) * BUFB, warpM, warpN, lid, acc1);
        }

        // ---- H epilogue: bias + tanh -> fp16 into smem H ----
        #pragma unroll
        for (int mt = 0; mt < 2; mt++) {
            const int r0 = warpM * 32 + mt * 16 + g;
            char* hrow0 = smem + HOFF + (size_t)r0 * HPITCH;
            char* hrow1 = hrow0 + 8 * HPITCH;
            #pragma unroll
            for (int nt = 0; nt < 4; nt++) {
                const int colP = warpN * 32 + nt * 8 + 2 * t;
                const float b0 = __ldg(&b_pair[p * EMBED + colP]);
                const float b1 = __ldg(&b_pair[p * EMBED + colP + 1]);
                *reinterpret_cast<__half2*>(hrow0 + colP * 2) =
                    __floats2half2_rn(tanhf(acc1[mt][nt][0] + b0), tanhf(acc1[mt][nt][1] + b1));
                *reinterpret_cast<__half2*>(hrow1 + colP * 2) =
                    __floats2half2_rn(tanhf(acc1[mt][nt][2] + b0), tanhf(acc1[mt][nt][3] + b1));
            }
        }
        __syncthreads();   // H visible to all warps; chunk buffers free

        // ---- GEMM2: 8 chunks over this pair's 256-wide K segment ----
        const __half* WF = g_Wft + (size_t)p * EMBED;  // column offset p*256 in [n][k]
        cp_b(sb, tid, WF, KFIN); CP_COMMIT();
        cp_b(sb + BUFB, tid, WF + KC, KFIN); CP_COMMIT();
        const int NCH2 = EMBED / KC;
        for (int c = 0; c < NCH2; c++) {
            if (c + 1 < NCH2) { CP_WAIT(1); } else { CP_WAIT(0); }
            __syncthreads();
            if (c + 2 < NCH2) {
                cp_b(sb + ((c + 2) % 3) * BUFB, tid, WF + (c + 2) * KC, KFIN);
                CP_COMMIT();
            }
            compute2(sb + (c % 3) * BUFB, hbase, c, warpM, warpN, lid, acc2);
        }
        __syncthreads();   // all buffers/H free before next pair
    }

    // ---- final epilogue: + b_final, fp32 out ----
    #pragma unroll
    for (int mt = 0; mt < 2; mt++) {
        const int r0 = rowBase + warpM * 32 + mt * 16 + g;
        #pragma unroll
        for (int nt = 0; nt < 4; nt++) {
            const int colG = warpN * 32 + nt * 8 + 2 * t;
            const float b0 = __ldg(&b_final[colG]);
            const float b1 = __ldg(&b_final[colG + 1]);
            float2 v0 = make_float2(acc2[mt][nt][0] + b0, acc2[mt][nt][1] + b1);
            float2 v1 = make_float2(acc2[mt][nt][2] + b0, acc2[mt][nt][3] + b1);
            *reinterpret_cast<float2*>(out + (size_t)r0 * EMBED + colG)       = v0;
            *reinterpret_cast<float2*>(out + (size_t)(r0 + 8) * EMBED + colG) = v1;
        }
    }
}

extern "C" void kernel_launch(void* const* d_in, const int* in_sizes, int n_in,
                              void* d_out, int out_size)
{
    const float* features = (const float*)d_in[0];
    const float* W_pair   = (const float*)d_in[1];
    const float* b_pair   = (const float*)d_in[2];
    const float* W_final  = (const float*)d_in[3];
    const float* b_final  = (const float*)d_in[4];
    const int*   NAS      = (const int*)d_in[5];
    float* out = (float*)d_out;

    cudaFuncSetAttribute(fused_mma, cudaFuncAttributeMaxDynamicSharedMemorySize, SMEM_BYTES);

    prep_wpair <<<dim3(KPAIR/32, EMBED/32, PAIRS), dim3(32, 8)>>>(W_pair, NAS);
    prep_wfinal<<<dim3(KFIN/32,  EMBED/32),        dim3(32, 8)>>>(W_final, NAS);

    fused_mma<<<dim3(MROWS/BM), NTHREADS, SMEM_BYTES>>>(features, b_pair, b_final, NAS, out);
}

// round 11
// speedup vs baseline: 4.6192x; 1.2062x over previous
#include <cuda_runtime.h>
#include <cuda_fp16.h>
#include <cstdint>
#include <math.h>

#define EMBED 256
#define PAIRS 15
#define MROWS 16384
#define KPAIR 512
#define KFIN  3840

#define BM 64
#define KC 32
#define NTHREADS 512
#define PITCH 80                          // A/B smem row: 32 fp16 = 64B + 16B pad
#define ATILE (64 * PITCH)                // 5120 B
#define BTILE (256 * PITCH)               // 20480 B
#define BUFB  (ATILE + BTILE)             // 25600 B  [A][B]
#define HPITCH 528                        // 64-row H tile: 256 fp16 + 16B pad
#define HOFF  (3 * BUFB)                  // 76800
#define SMEM_BYTES (HOFF + 64 * HPITCH)   // 110592

// ---- scratch (static device globals; allocation-guard-safe) ----
static __device__ __half g_Wpt[(size_t)PAIRS * EMBED * KPAIR];  // [p][n][k] fp16
static __device__ __half g_Wft[(size_t)EMBED * KFIN];           // [n][k]   fp16

__constant__ int c_pi[PAIRS] = {0,0,0,0,0,1,1,1,1,2,2,2,3,3,4};
__constant__ int c_pj[PAIRS] = {1,2,3,4,5,2,3,4,5,3,4,5,4,5,5};

__device__ __forceinline__ bool pair_on(const int* __restrict__ NAS, int p) {
    int i = c_pi[p], j = c_pj[p];
    int ni = (i < 2) ? 1 : __ldg(&NAS[i]);
    int nj = (j < 2) ? 1 : __ldg(&NAS[j]);
    return (ni != 0) && (nj != 0);
}
__device__ __forceinline__ uint32_t smem_u32(const void* p) {
    uint32_t a;
    asm("{ .reg .u64 t; cvta.to.shared.u64 t, %1; cvt.u32.u64 %0, t; }" : "=r"(a) : "l"(p));
    return a;
}

// ---- base-target PTX primitives (sm_80 baseline; valid on plain sm_103) ----
__device__ __forceinline__ void cp16(uint32_t dst, const void* src) {
    asm volatile("cp.async.cg.shared.global [%0], [%1], 16;" :: "r"(dst), "l"(src));
}
#define CP_COMMIT()      asm volatile("cp.async.commit_group;" ::: "memory")
#define CP_WAIT(n)       asm volatile("cp.async.wait_group %0;" :: "n"(n) : "memory")
#define LDM_X4(r, addr) \
    asm volatile("ldmatrix.sync.aligned.m8n8.x4.shared.b16 {%0,%1,%2,%3}, [%4];" \
        : "=r"((r)[0]), "=r"((r)[1]), "=r"((r)[2]), "=r"((r)[3]) : "r"(addr))
#define LDS32(v, addr) \
    asm volatile("ld.shared.b32 %0, [%1];" : "=r"(v) : "r"(addr))
#define MMA(d, a, b0, b1) \
    asm volatile("mma.sync.aligned.m16n8k16.row.col.f32.f16.f16.f32 " \
        "{%0,%1,%2,%3}, {%4,%5,%6,%7}, {%8,%9}, {%0,%1,%2,%3};" \
        : "+f"((d)[0]), "+f"((d)[1]), "+f"((d)[2]), "+f"((d)[3]) \
        : "r"((a)[0]), "r"((a)[1]), "r"((a)[2]), "r"((a)[3]), "r"(b0), "r"(b1))

// ---------------------------------------------------------------------------
// Prep: transpose weights to [n][k], fp16.
// ---------------------------------------------------------------------------
__global__ void prep_wpair(const float* __restrict__ W_pair, const int* __restrict__ NAS) {
    int p = blockIdx.z;
    if (!pair_on(NAS, p)) return;
    __shared__ float tsh[32][33];
    int k0 = blockIdx.x * 32, n0 = blockIdx.y * 32;
    int tx = threadIdx.x, ty = threadIdx.y;
    const float* W = W_pair + (size_t)p * KPAIR * EMBED;
    #pragma unroll
    for (int i = 0; i < 4; i++)
        tsh[ty + i*8][tx] = W[(size_t)(k0 + ty + i*8) * EMBED + n0 + tx];
    __syncthreads();
    #pragma unroll
    for (int i = 0; i < 4; i++) {
        size_t o = ((size_t)p * EMBED + n0 + ty + i*8) * KPAIR + k0 + tx;
        g_Wpt[o] = __float2half_rn(tsh[tx][ty + i*8]);
    }
}

__global__ void prep_wfinal(const float* __restrict__ W_final, const int* __restrict__ NAS) {
    int k0 = blockIdx.x * 32;
    if (!pair_on(NAS, k0 >> 8)) return;
    __shared__ float tsh[32][33];
    int n0 = blockIdx.y * 32;
    int tx = threadIdx.x, ty = threadIdx.y;
    #pragma unroll
    for (int i = 0; i < 4; i++)
        tsh[ty + i*8][tx] = W_final[(size_t)(k0 + ty + i*8) * EMBED + n0 + tx];
    __syncthreads();
    #pragma unroll
    for (int i = 0; i < 4; i++) {
        size_t o = (size_t)(n0 + ty + i*8) * KFIN + k0 + tx;
        g_Wft[o] = __float2half_rn(tsh[tx][ty + i*8]);
    }
}

// ---------------------------------------------------------------------------
// Loaders
// ---------------------------------------------------------------------------
__device__ __forceinline__ void lda_regs(float4 r[2], const float* __restrict__ s) {
    r[0] = *reinterpret_cast<const float4*>(s);
    r[1] = *reinterpret_cast<const float4*>(s + 4);
}
// A (GEMM1): 64 rows x 32 k, fp32 -> fp16 (single); threads 0..255 (4/row x 8 elems).
__device__ __forceinline__ void sts_cvt(char* smem, int bufofs, uint32_t dofs,
                                        const float4 r[2]) {
    float f[8] = {r[0].x, r[0].y, r[0].z, r[0].w, r[1].x, r[1].y, r[1].z, r[1].w};
    unsigned short h[8];
    #pragma unroll
    for (int q = 0; q < 8; q++)
        h[q] = __half_as_ushort(__float2half_rn(f[q]));
    *reinterpret_cast<uint4*>(smem + bufofs + dofs) =
        make_uint4((uint32_t)h[0] | ((uint32_t)h[1] << 16), (uint32_t)h[2] | ((uint32_t)h[3] << 16),
                   (uint32_t)h[4] | ((uint32_t)h[5] << 16), (uint32_t)h[6] | ((uint32_t)h[7] << 16));
}
// B tile: 256 rows(n) x 32 k fp16, 2 threads/row (512 threads).
__device__ __forceinline__ void cp_b(uint32_t buf, int tid, const __half* bsrc, size_t stride) {
    const int row = tid >> 1, h = tid & 1;
    const uint32_t d = buf + ATILE + row * PITCH + h * 32;
    const __half* s = bsrc + (size_t)row * stride + h * 16;
    cp16(d, s); cp16(d + 16, s + 8);
}

// ---------------------------------------------------------------------------
// Compute. 16 warps: warpM = wid&1 (32 rows), warpN = wid>>1 (32 cols of 256).
// A single fp16 tile -> 2 MMAs per (mt,nt).
// ---------------------------------------------------------------------------
__device__ __forceinline__ void compute1(uint32_t buf, int warpM, int warpN,
                                         int lid, float acc[2][4][4]) {
    const int arow = lid & 15, ka = (lid >> 4) & 1;
    const int g = lid >> 2, t = lid & 3;
    const uint32_t bbase = buf + ATILE + (warpN * 32 + g) * PITCH + t * 4;
    #pragma unroll
    for (int ks = 0; ks < 2; ks++) {
        uint32_t a[2][4];
        #pragma unroll
        for (int mt = 0; mt < 2; mt++) {
            uint32_t ad = buf + (warpM*32 + mt*16 + arow) * PITCH + ks*32 + ka*16;
            LDM_X4(a[mt], ad);
        }
        #pragma unroll
        for (int nt = 0; nt < 4; nt++) {
            uint32_t bd = bbase + nt * 8 * PITCH + ks * 32;
            uint32_t b0, b1;
            LDS32(b0, bd); LDS32(b1, bd + 16);
            MMA(acc[0][nt], a[0], b0, b1);
            MMA(acc[1][nt], a[1], b0, b1);
        }
    }
}
// GEMM2: A = H in smem (fp16), B in chunk buffer.
__device__ __forceinline__ void compute2(uint32_t buf, uint32_t hbase, int c2,
                                         int warpM, int warpN, int lid, float acc[2][4][4]) {
    const int arow = lid & 15, ka = (lid >> 4) & 1;
    const int g = lid >> 2, t = lid & 3;
    const uint32_t bbase = buf + ATILE + (warpN * 32 + g) * PITCH + t * 4;
    #pragma unroll
    for (int ks = 0; ks < 2; ks++) {
        uint32_t a[2][4];
        #pragma unroll
        for (int mt = 0; mt < 2; mt++) {
            uint32_t ad = hbase + (warpM*32 + mt*16 + arow) * HPITCH
                        + c2*64 + ks*32 + ka*16;
            LDM_X4(a[mt], ad);
        }
        #pragma unroll
        for (int nt = 0; nt < 4; nt++) {
            uint32_t bd = bbase + nt * 8 * PITCH + ks * 32;
            uint32_t b0, b1;
            LDS32(b0, bd); LDS32(b1, bd + 16);
            MMA(acc[0][nt], a[0], b0, b1);
            MMA(acc[1][nt], a[1], b0, b1);
        }
    }
}

// ---------------------------------------------------------------------------
// Fused kernel: per 64-row block, loop active pairs:
//   H = tanh([Fi|Fj] @ Wp + bp) (smem)  ;  out_acc += H @ Wft[p]
// ---------------------------------------------------------------------------
__global__ __launch_bounds__(NTHREADS, 1)
void fused_mma(const float* __restrict__ features,
               const float* __restrict__ b_pair,
               const float* __restrict__ b_final,
               const int*   __restrict__ NAS,
               float*       __restrict__ out)
{
    const int rowBase = blockIdx.x * BM;
    extern __shared__ char smem[];
    const uint32_t sb = smem_u32(smem);
    const uint32_t hbase = sb + HOFF;
    const int tid = threadIdx.x, wid = tid >> 5, lid = tid & 31;
    const int warpM = wid & 1, warpN = wid >> 1;
    const int g = lid >> 2, t = lid & 3;
    const bool aldr = (tid < 256);

    // A-loader lane mapping (threads 0..255; 4 threads/row x 8 fp32)
    const int arow = tid & 63, aq = (tid >> 6) & 3;
    const uint32_t adofs = arow * PITCH + aq * 16;             // smem bytes
    const size_t   arofs = (size_t)arow * EMBED + aq * 8;      // gmem elems

    int plist[PAIRS], nact = 0;
    #pragma unroll
    for (int p = 0; p < PAIRS; p++)
        if (pair_on(NAS, p)) plist[nact++] = p;

    float acc2[2][4][4];
    #pragma unroll
    for (int i = 0; i < 2; i++)
        #pragma unroll
        for (int j = 0; j < 4; j++)
            #pragma unroll
            for (int e = 0; e < 4; e++) acc2[i][j][e] = 0.0f;

    for (int pi = 0; pi < nact; pi++) {
        const int p = plist[pi];
        const float* Fi = features + ((size_t)c_pi[p] * MROWS + rowBase) * EMBED;
        const float* Fj = features + ((size_t)c_pj[p] * MROWS + rowBase) * EMBED;
        const __half* WB = g_Wpt + (size_t)p * EMBED * KPAIR;

        float acc1[2][4][4];
        #pragma unroll
        for (int i = 0; i < 2; i++)
            #pragma unroll
            for (int j = 0; j < 4; j++)
                #pragma unroll
                for (int e = 0; e < 4; e++) acc1[i][j][e] = 0.0f;

        // ---- GEMM1: 16 chunks over K=512, triple-buffered ----
        const int NCH1 = KPAIR / KC;
        float4 rA[2];
        if (aldr) {
            lda_regs(rA, Fi + arofs);
            sts_cvt(smem, 0, adofs, rA);
        }
        cp_b(sb, tid, WB, KPAIR); CP_COMMIT();
        if (aldr) lda_regs(rA, Fi + arofs + KC);
        cp_b(sb + BUFB, tid, WB + KC, KPAIR); CP_COMMIT();

        for (int c = 0; c < NCH1; c++) {
            if (aldr) {
                if (c + 1 < NCH1) sts_cvt(smem, ((c + 1) % 3) * BUFB, adofs, rA);
                if (c + 2 < NCH1) {
                    const int k0 = (c + 2) * KC;
                    const float* base = (k0 < EMBED) ? Fi : Fj;
                    lda_regs(rA, base + arofs + (k0 & (EMBED - 1)));
                }
            }
            if (c + 1 < NCH1) { CP_WAIT(1); } else { CP_WAIT(0); }
            __syncthreads();
            if (c + 2 < NCH1) {
                cp_b(sb + ((c + 2) % 3) * BUFB, tid, WB + (c + 2) * KC, KPAIR);
                CP_COMMIT();
            }
            compute1(sb + (c % 3) * BUFB, warpM, warpN, lid, acc1);
        }

        // ---- H epilogue: bias + tanh -> fp16 into smem H ----
        #pragma unroll
        for (int mt = 0; mt < 2; mt++) {
            const int r0 = warpM * 32 + mt * 16 + g;
            char* hrow0 = smem + HOFF + (size_t)r0 * HPITCH;
            char* hrow1 = hrow0 + 8 * HPITCH;
            #pragma unroll
            for (int nt = 0; nt < 4; nt++) {
                const int colP = warpN * 32 + nt * 8 + 2 * t;
                const float b0 = __ldg(&b_pair[p * EMBED + colP]);
                const float b1 = __ldg(&b_pair[p * EMBED + colP + 1]);
                *reinterpret_cast<__half2*>(hrow0 + colP * 2) =
                    __floats2half2_rn(tanhf(acc1[mt][nt][0] + b0), tanhf(acc1[mt][nt][1] + b1));
                *reinterpret_cast<__half2*>(hrow1 + colP * 2) =
                    __floats2half2_rn(tanhf(acc1[mt][nt][2] + b0), tanhf(acc1[mt][nt][3] + b1));
            }
        }
        __syncthreads();   // H visible to all warps; chunk buffers free

        // ---- GEMM2: 8 chunks over this pair's 256-wide K segment ----
        const __half* WF = g_Wft + (size_t)p * EMBED;  // column offset p*256 in [n][k]
        cp_b(sb, tid, WF, KFIN); CP_COMMIT();
        cp_b(sb + BUFB, tid, WF + KC, KFIN); CP_COMMIT();
        const int NCH2 = EMBED / KC;
        for (int c = 0; c < NCH2; c++) {
            if (c + 1 < NCH2) { CP_WAIT(1); } else { CP_WAIT(0); }
            __syncthreads();
            if (c + 2 < NCH2) {
                cp_b(sb + ((c + 2) % 3) * BUFB, tid, WF + (c + 2) * KC, KFIN);
                CP_COMMIT();
            }
            compute2(sb + (c % 3) * BUFB, hbase, c, warpM, warpN, lid, acc2);
        }
        __syncthreads();   // all buffers/H free before next pair
    }

    // ---- final epilogue: + b_final, fp32 out ----
    #pragma unroll
    for (int mt = 0; mt < 2; mt++) {
        const int r0 = rowBase + warpM * 32 + mt * 16 + g;
        #pragma unroll
        for (int nt = 0; nt < 4; nt++) {
            const int colG = warpN * 32 + nt * 8 + 2 * t;
            const float b0 = __ldg(&b_final[colG]);
            const float b1 = __ldg(&b_final[colG + 1]);
            float2 v0 = make_float2(acc2[mt][nt][0] + b0, acc2[mt][nt][1] + b1);
            float2 v1 = make_float2(acc2[mt][nt][2] + b0, acc2[mt][nt][3] + b1);
            *reinterpret_cast<float2*>(out + (size_t)r0 * EMBED + colG)       = v0;
            *reinterpret_cast<float2*>(out + (size_t)(r0 + 8) * EMBED + colG) = v1;
        }
    }
}

extern "C" void kernel_launch(void* const* d_in, const int* in_sizes, int n_in,
                              void* d_out, int out_size)
{
    const float* features = (const float*)d_in[0];
    const float* W_pair   = (const float*)d_in[1];
    const float* b_pair   = (const float*)d_in[2];
    const float* W_final  = (const float*)d_in[3];
    const float* b_final  = (const float*)d_in[4];
    const int*   NAS      = (const int*)d_in[5];
    float* out = (float*)d_out;

    cudaFuncSetAttribute(fused_mma, cudaFuncAttributeMaxDynamicSharedMemorySize, SMEM_BYTES);

    prep_wpair <<<dim3(KPAIR/32, EMBED/32, PAIRS), dim3(32, 8)>>>(W_pair, NAS);
    prep_wfinal<<<dim3(KFIN/32,  EMBED/32),        dim3(32, 8)>>>(W_final, NAS);

    fused_mma<<<dim3(MROWS/BM), NTHREADS, SMEM_BYTES>>>(features, b_pair, b_final, NAS, out);
}